// round 10
// baseline (speedup 1.0000x reference)
#include <cuda_runtime.h>
#include <cuda_bf16.h>
#include <math.h>
#include <stdint.h>

#define B_  4
#define T_  2048
#define C_  1024
#define H_  16
#define D_  64
#define C3_ 3072
#define K3_ 3072

typedef unsigned long long u64;

__device__ float g_qkv[(size_t)B_ * T_ * C3_];
__device__ __nv_bfloat16 g_A3[(size_t)B_ * T_ * K3_];
__device__ __nv_bfloat16 g_B3[(size_t)C3_ * K3_];
__device__ __nv_bfloat16 g_K[(size_t)B_ * H_ * T_ * 128];
__device__ __nv_bfloat16 g_V[(size_t)B_ * H_ * T_ * 128];

// ---- helpers ----
__device__ __forceinline__ uint32_t smem_u32(const void* p) {
    uint32_t a;
    asm("{ .reg .u64 t; cvta.to.shared.u64 t, %1; cvt.u32.u64 %0, t; }" : "=r"(a) : "l"(p));
    return a;
}
__device__ __forceinline__ void cp16(uint32_t dst, const void* src) {
    asm volatile("cp.async.cg.shared.global [%0], [%1], 16;" :: "r"(dst), "l"(src));
}
__device__ __forceinline__ void ldsm_x4(uint32_t& r0, uint32_t& r1, uint32_t& r2, uint32_t& r3,
                                        uint32_t addr) {
    asm volatile("ldmatrix.sync.aligned.m8n8.x4.shared.b16 {%0,%1,%2,%3},[%4];"
                 : "=r"(r0), "=r"(r1), "=r"(r2), "=r"(r3) : "r"(addr));
}
__device__ __forceinline__ void ldsm_x4t(uint32_t& r0, uint32_t& r1, uint32_t& r2, uint32_t& r3,
                                         uint32_t addr) {
    asm volatile("ldmatrix.sync.aligned.m8n8.x4.trans.shared.b16 {%0,%1,%2,%3},[%4];"
                 : "=r"(r0), "=r"(r1), "=r"(r2), "=r"(r3) : "r"(addr));
}
__device__ __forceinline__ void mma16816(float* c, const uint32_t* a, uint32_t b0, uint32_t b1) {
    asm volatile(
        "mma.sync.aligned.m16n8k16.row.col.f32.bf16.bf16.f32 "
        "{%0,%1,%2,%3},{%4,%5,%6,%7},{%8,%9},{%0,%1,%2,%3};"
        : "+f"(c[0]), "+f"(c[1]), "+f"(c[2]), "+f"(c[3])
        : "r"(a[0]), "r"(a[1]), "r"(a[2]), "r"(a[3]), "r"(b0), "r"(b1));
}
__device__ __forceinline__ uint32_t pkbf(float lo, float hi) {
    uint32_t r; asm("cvt.rn.bf16x2.f32 %0,%1,%2;" : "=r"(r) : "f"(hi), "f"(lo)); return r;
}
__device__ __forceinline__ uint32_t split2(float a, float b, uint32_t& lo) {
    uint32_t hp = pkbf(a, b);
    float la = a - __uint_as_float(hp << 16);
    float lb = b - __uint_as_float(hp & 0xFFFF0000u);
    lo = pkbf(la, lb);
    return hp;
}
__device__ __forceinline__ uint2 split4(float4 f, uint2& lo) {
    uint32_t l0, l1;
    uint32_t h0 = split2(f.x, f.y, l0);
    uint32_t h1 = split2(f.z, f.w, l1);
    lo = make_uint2(l0, l1);
    return make_uint2(h0, h1);
}

// ---------------------------------------------------------------------------
// split_A: src fp32 [M,1024] -> dst bf16 [M,3072] = [hi|lo|hi]
// ---------------------------------------------------------------------------
__global__ __launch_bounds__(256) void split_A(
    const float* __restrict__ src, __nv_bfloat16* __restrict__ dst)
{
    size_t idx = ((size_t)blockIdx.x * 256 + threadIdx.x) * 8;
    int m = (int)(idx >> 10), k = (int)(idx & 1023);
    float4 f0 = *(const float4*)(src + idx);
    float4 f1 = *(const float4*)(src + idx + 4);
    uint2 l0, l1;
    uint2 h0 = split4(f0, l0);
    uint2 h1 = split4(f1, l1);
    __nv_bfloat16* r = dst + (size_t)m * K3_;
    *(uint4*)(r + k)        = make_uint4(h0.x, h0.y, h1.x, h1.y);
    *(uint4*)(r + 1024 + k) = make_uint4(l0.x, l0.y, l1.x, l1.y);
    *(uint4*)(r + 2048 + k) = make_uint4(h0.x, h0.y, h1.x, h1.y);
}

// ---------------------------------------------------------------------------
// prep_W: W fp32 [1024, N] -> Bo bf16 [N,3072] = [hi|hi|lo]
// ---------------------------------------------------------------------------
__global__ __launch_bounds__(256) void prep_W(
    const float* __restrict__ W, __nv_bfloat16* __restrict__ Bo, int N)
{
    __shared__ float t[32][33];
    int n0 = blockIdx.x * 32, k0 = blockIdx.y * 32;
    {
        int tx = threadIdx.x & 31, ty = threadIdx.x >> 5;
        #pragma unroll
        for (int i = 0; i < 4; i++)
            t[ty + i * 8][tx] = W[(size_t)(k0 + ty + i * 8) * N + n0 + tx];
    }
    __syncthreads();
    int kk = (threadIdx.x & 15) * 2, ny = threadIdx.x >> 4;
    #pragma unroll
    for (int i = 0; i < 2; i++) {
        int n = ny + i * 16;
        uint32_t lp;
        uint32_t hp = split2(t[kk][n], t[kk + 1][n], lp);
        size_t r = (size_t)(n0 + n) * K3_;
        *(uint32_t*)(Bo + r + k0 + kk)        = hp;
        *(uint32_t*)(Bo + r + 1024 + k0 + kk) = hp;
        *(uint32_t*)(Bo + r + 2048 + k0 + kk) = lp;
    }
}

// ---------------------------------------------------------------------------
// HMMA GEMM: 256x128 CTA tile, BK=64, 3-stage cp.async, 8 warps of 64x64.
// ---------------------------------------------------------------------------
#define BK    64
#define ROWE  72     // 64 data + 8 pad
#define NSTG  3
#define ABYTES (256 * ROWE * 2)
#define BBYTES (128 * ROWE * 2)
#define STGBYTES (ABYTES + BBYTES)

__global__ __launch_bounds__(256) void hmma_gemm(
    const __nv_bfloat16* __restrict__ A, const __nv_bfloat16* __restrict__ Bk,
    const float* __restrict__ bias, float* __restrict__ Cout,
    int M, int N, int K)
{
    extern __shared__ __align__(16) __nv_bfloat16 gsm[];

    const int tid  = threadIdx.x;
    const int lane = tid & 31;
    const int wid  = tid >> 5;
    const int wm   = wid >> 1;          // 0..3 -> m offset wm*64
    const int wn   = wid & 1;           // 0..1 -> n offset wn*64
    const int m0 = blockIdx.y * 256, n0 = blockIdx.x * 128;

    const uint32_t smb = smem_u32(gsm);

    auto load_tile = [&](int stg, int kt) {
        const __nv_bfloat16* Ag = A + (size_t)m0 * K + kt * BK;
        const __nv_bfloat16* Bg = Bk + (size_t)n0 * K + kt * BK;
        uint32_t sA = smb + stg * STGBYTES;
        uint32_t sB = sA + ABYTES;
        #pragma unroll
        for (int it = 0; it < 8; it++) {       // A: 2048 chunks
            int c = tid + it * 256;
            int row = c >> 3, seg = c & 7;
            cp16(sA + (uint32_t)(row * ROWE + seg * 8) * 2, Ag + (size_t)row * K + seg * 8);
        }
        #pragma unroll
        for (int it = 0; it < 4; it++) {       // B: 1024 chunks
            int c = tid + it * 256;
            int row = c >> 3, seg = c & 7;
            cp16(sB + (uint32_t)(row * ROWE + seg * 8) * 2, Bg + (size_t)row * K + seg * 8);
        }
        asm volatile("cp.async.commit_group;" ::: "memory");
    };

    float acc[4][8][4];
    #pragma unroll
    for (int i = 0; i < 4; i++)
        #pragma unroll
        for (int j = 0; j < 8; j++)
            #pragma unroll
            for (int e = 0; e < 4; e++) acc[i][j][e] = 0.f;

    const int nkt = K / BK;   // 48
    load_tile(0, 0);
    load_tile(1, 1);

    const int a_row = wm * 64 + (lane & 15);
    const int a_ko  = (lane >> 4) * 8;
    const int b_row = wn * 64 + (lane & 7) + ((lane >> 4) & 1) * 8;
    const int b_ko  = ((lane >> 3) & 1) * 8;

    int stg = 0;
    for (int kt = 0; kt < nkt; kt++) {
        if (kt + 2 < nkt) {
            int s2 = stg + 2; if (s2 >= NSTG) s2 -= NSTG;
            load_tile(s2, kt + 2);
        } else {
            asm volatile("cp.async.commit_group;" ::: "memory");
        }
        asm volatile("cp.async.wait_group 2;" ::: "memory");
        __syncthreads();

        const uint32_t aT = smb + stg * STGBYTES;
        const uint32_t bT = aT + ABYTES;

        #pragma unroll
        for (int ks = 0; ks < 4; ks++) {
            uint32_t af[4][4];
            #pragma unroll
            for (int mi = 0; mi < 4; mi++)
                ldsm_x4(af[mi][0], af[mi][1], af[mi][2], af[mi][3],
                        aT + (uint32_t)((a_row + mi * 16) * ROWE + ks * 16 + a_ko) * 2);
            uint32_t bf[8][2];
            #pragma unroll
            for (int nb = 0; nb < 4; nb++) {
                uint32_t r0, r1, r2, r3;
                ldsm_x4(r0, r1, r2, r3,
                        bT + (uint32_t)((b_row + nb * 16) * ROWE + ks * 16 + b_ko) * 2);
                bf[nb * 2][0] = r0; bf[nb * 2][1] = r1;
                bf[nb * 2 + 1][0] = r2; bf[nb * 2 + 1][1] = r3;
            }
            #pragma unroll
            for (int mi = 0; mi < 4; mi++)
                #pragma unroll
                for (int ni = 0; ni < 8; ni++)
                    mma16816(acc[mi][ni], af[mi], bf[ni][0], bf[ni][1]);
        }
        __syncthreads();
        if (++stg >= NSTG) stg = 0;
    }

    #pragma unroll
    for (int mi = 0; mi < 4; mi++) {
        int row_g = m0 + wm * 64 + mi * 16 + (lane >> 2);
        #pragma unroll
        for (int ni = 0; ni < 8; ni++) {
            int col_g = n0 + wn * 64 + ni * 8 + (lane & 3) * 2;
            float b0 = bias[col_g], b1 = bias[col_g + 1];
            float2 o0 = make_float2(acc[mi][ni][0] + b0, acc[mi][ni][1] + b1);
            float2 o1 = make_float2(acc[mi][ni][2] + b0, acc[mi][ni][3] + b1);
            *(float2*)(Cout + (size_t)row_g * N + col_g) = o0;
            *(float2*)(Cout + (size_t)(row_g + 8) * N + col_g) = o1;
        }
    }
}

// ---------------------------------------------------------------------------
// Sparsemax over K head-dim + fused split of K AND V into bf16 [hi|lo] rows.
// ---------------------------------------------------------------------------
__global__ __launch_bounds__(256) void sparsemax_kv(
    const float* __restrict__ qkv,
    __nv_bfloat16* __restrict__ Ko, __nv_bfloat16* __restrict__ Vo)
{
    const int lane = threadIdx.x & 31;
    const int wrp  = threadIdx.x >> 5;
    const size_t row = (size_t)blockIdx.x * 8 + wrp;
    const size_t bt  = row >> 4;
    const int    h   = (int)(row & 15);
    const int    b   = (int)(bt >> 11);
    const int    t   = (int)(bt & 2047);

    const float* pk = qkv + bt * C3_ + C_ + h * D_;
    float2 z = *(const float2*)(pk + 2 * lane);
    float v0 = z.x, v1 = z.y;

    #pragma unroll
    for (int k = 2; k <= 64; k <<= 1) {
        #pragma unroll
        for (int j = k >> 1; j > 0; j >>= 1) {
            if (j < 32) {
                float p0 = __shfl_xor_sync(0xffffffffu, v0, j);
                float p1 = __shfl_xor_sync(0xffffffffu, v1, j);
                bool lower = (lane & j) == 0;
                bool up0 = (lane & k) != 0;
                bool up1 = ((lane + 32) & k) != 0;
                v0 = (lower == up0) ? fminf(v0, p0) : fmaxf(v0, p0);
                v1 = (lower == up1) ? fminf(v1, p1) : fmaxf(v1, p1);
            } else {
                float a = fmaxf(v0, v1), bmin = fminf(v0, v1);
                v0 = a; v1 = bmin;
            }
        }
    }

    float c0 = v0;
    #pragma unroll
    for (int o = 1; o < 32; o <<= 1) {
        float tt = __shfl_up_sync(0xffffffffu, c0, o);
        if (lane >= o) c0 += tt;
    }
    float c1 = v1;
    #pragma unroll
    for (int o = 1; o < 32; o <<= 1) {
        float tt = __shfl_up_sync(0xffffffffu, c1, o);
        if (lane >= o) c1 += tt;
    }
    c1 += __shfl_sync(0xffffffffu, c0, 31);

    bool s0 = 1.f + (float)(lane + 1)  * v0 > c0;
    bool s1 = 1.f + (float)(lane + 33) * v1 > c1;
    int rho = __popc(__ballot_sync(0xffffffffu, s0)) +
              __popc(__ballot_sync(0xffffffffu, s1));
    int ridx = rho - 1;
    float csA = __shfl_sync(0xffffffffu, c0, ridx & 31);
    float csB = __shfl_sync(0xffffffffu, c1, ridx & 31);
    float cs  = (ridx < 32) ? csA : csB;
    float tau = (cs - 1.f) / (float)rho;

    float k0 = fmaxf(z.x - tau, 0.f), k1 = fmaxf(z.y - tau, 0.f);
    uint32_t klo; uint32_t khi = split2(k0, k1, klo);
    __nv_bfloat16* kr = Ko + ((size_t)(b * H_ + h) * T_ + t) * 128;
    *(uint32_t*)(kr + 2 * lane)      = khi;
    *(uint32_t*)(kr + 64 + 2 * lane) = klo;

    float2 vv = *(const float2*)(pk + C_ + 2 * lane);
    uint32_t vlo; uint32_t vhi = split2(vv.x, vv.y, vlo);
    __nv_bfloat16* vr = Vo + ((size_t)(b * H_ + h) * T_ + t) * 128;
    *(uint32_t*)(vr + 2 * lane)      = vhi;
    *(uint32_t*)(vr + 64 + 2 * lane) = vlo;
}

// ---------------------------------------------------------------------------
// Flash attention (LPT ordering), cp.async K/V, fused XSA, split-A3 epilogue.
// ---------------------------------------------------------------------------
#define FROW 136
#define FBUF (128 * FROW)

__global__ __launch_bounds__(256) void flash_hmma(
    const float* __restrict__ qkv,
    const __nv_bfloat16* __restrict__ Ks, const __nv_bfloat16* __restrict__ Vs,
    __nv_bfloat16* __restrict__ A3out)
{
    extern __shared__ __align__(16) __nv_bfloat16 smx[];

    const int tid  = threadIdx.x;
    const int lane = tid & 31;
    const int w    = tid >> 5;
    const int qt = (int)gridDim.x - 1 - (int)blockIdx.x;
    const int h = blockIdx.y, b = blockIdx.z;
    const size_t base = (size_t)b * T_ * C3_;

    const __nv_bfloat16* Kb = Ks + (size_t)(b * H_ + h) * T_ * 128;
    const __nv_bfloat16* Vb = Vs + (size_t)(b * H_ + h) * T_ * 128;
    const uint32_t smb0 = smem_u32(smx);

    auto load_tile = [&](int buf, int kt) {
        const __nv_bfloat16* kg = Kb + (size_t)kt * 64 * 128;
        const __nv_bfloat16* vg = Vb + (size_t)kt * 64 * 128;
        uint32_t sb = smb0 + buf * (FBUF * 2);
        #pragma unroll
        for (int it = 0; it < 4; it++) {
            int c = tid + it * 256;
            int j = c >> 4, seg = c & 15;
            cp16(sb + (uint32_t)(j * FROW) * 2 + seg * 16,        kg + j * 128 + seg * 8);
            cp16(sb + (uint32_t)((64 + j) * FROW) * 2 + seg * 16, vg + j * 128 + seg * 8);
        }
        asm volatile("cp.async.commit_group;" ::: "memory");
    };

    load_tile(0, 0);
    {
        __nv_bfloat16* qb = smx + FBUF;
        for (int i = tid; i < 2048; i += 256) {
            int row = i >> 4, d = (i & 15) * 4;
            float4 f4 = *(const float4*)(qkv + base + (size_t)(qt * 128 + row) * C3_ + h * D_ + d);
            f4.x *= 0.125f; f4.y *= 0.125f; f4.z *= 0.125f; f4.w *= 0.125f;
            uint2 lo; uint2 hi = split4(f4, lo);
            *(uint2*)&qb[row * FROW + d]      = hi;
            *(uint2*)&qb[row * FROW + 64 + d] = lo;
        }
    }
    __syncthreads();

    uint32_t qf[8][4];
    #pragma unroll
    for (int kb = 0; kb < 8; kb++) {
        uint32_t addr = smb0 + FBUF * 2 +
                        (uint32_t)((w * 16 + (lane & 15)) * FROW + kb * 16 + (lane >> 4) * 8) * 2;
        ldsm_x4(qf[kb][0], qf[kb][1], qf[kb][2], qf[kb][3], addr);
    }
    __syncthreads();

    float o[8][4];
    #pragma unroll
    for (int nb = 0; nb < 8; nb++)
        #pragma unroll
        for (int e = 0; e < 4; e++) o[nb][e] = 0.f;
    float m0 = -1e30f, m1 = -1e30f, l0 = 0.f, l1 = 0.f;

    const int qrow_g0 = qt * 128 + w * 16 + (lane >> 2);
    const int nkt = (qt + 1) * 2;

    for (int kt = 0; kt < nkt; kt++) {
        if (kt + 1 < nkt) load_tile((kt + 1) & 1, kt + 1);
        else asm volatile("cp.async.commit_group;" ::: "memory");
        asm volatile("cp.async.wait_group 1;" ::: "memory");
        __syncthreads();

        const uint32_t smb = smb0 + (kt & 1) * (FBUF * 2);

        float s[8][4];
        #pragma unroll
        for (int nb = 0; nb < 8; nb++)
            #pragma unroll
            for (int e = 0; e < 4; e++) s[nb][e] = 0.f;

        #pragma unroll
        for (int kb = 0; kb < 12; kb++) {
            int bcol = (kb < 4) ? kb * 16 : ((kb < 8) ? (kb - 4) * 16 : 64 + (kb - 8) * 16);
            const uint32_t* af = (kb < 8) ? qf[kb] : qf[kb - 8];
            #pragma unroll
            for (int nbp = 0; nbp < 4; nbp++) {
                uint32_t r0, r1, r2, r3;
                uint32_t addr = smb +
                    (uint32_t)((nbp * 16 + (lane & 7) + ((lane >> 4) & 1) * 8) * FROW
                               + bcol + ((lane >> 3) & 1) * 8) * 2;
                ldsm_x4(r0, r1, r2, r3, addr);
                mma16816(s[nbp * 2],     af, r0, r1);
                mma16816(s[nbp * 2 + 1], af, r2, r3);
            }
        }

        if (kt * 64 + 63 > qt * 128 + w * 16) {
            #pragma unroll
            for (int nb = 0; nb < 8; nb++) {
                int col = kt * 64 + nb * 8 + (lane & 3) * 2;
                if (col     > qrow_g0)     s[nb][0] = -1e30f;
                if (col + 1 > qrow_g0)     s[nb][1] = -1e30f;
                if (col     > qrow_g0 + 8) s[nb][2] = -1e30f;
                if (col + 1 > qrow_g0 + 8) s[nb][3] = -1e30f;
            }
        }

        float tm0 = -1e30f, tm1 = -1e30f;
        #pragma unroll
        for (int nb = 0; nb < 8; nb++) {
            tm0 = fmaxf(tm0, fmaxf(s[nb][0], s[nb][1]));
            tm1 = fmaxf(tm1, fmaxf(s[nb][2], s[nb][3]));
        }
        tm0 = fmaxf(tm0, __shfl_xor_sync(0xffffffffu, tm0, 1));
        tm0 = fmaxf(tm0, __shfl_xor_sync(0xffffffffu, tm0, 2));
        tm1 = fmaxf(tm1, __shfl_xor_sync(0xffffffffu, tm1, 1));
        tm1 = fmaxf(tm1, __shfl_xor_sync(0xffffffffu, tm1, 2));

        float m0n = fmaxf(m0, tm0), m1n = fmaxf(m1, tm1);
        float corr0 = __expf(m0 - m0n), corr1 = __expf(m1 - m1n);
        m0 = m0n; m1 = m1n;
        l0 *= corr0; l1 *= corr1;

        #pragma unroll
        for (int nb = 0; nb < 8; nb++) {
            s[nb][0] = __expf(s[nb][0] - m0);
            s[nb][1] = __expf(s[nb][1] - m0);
            s[nb][2] = __expf(s[nb][2] - m1);
            s[nb][3] = __expf(s[nb][3] - m1);
            l0 += s[nb][0] + s[nb][1];
            l1 += s[nb][2] + s[nb][3];
            o[nb][0] *= corr0; o[nb][1] *= corr0;
            o[nb][2] *= corr1; o[nb][3] *= corr1;
        }

        uint32_t Ph[4][4], Pl[4][4];
        #pragma unroll
        for (int kb = 0; kb < 4; kb++) {
            #pragma unroll
            for (int q = 0; q < 4; q++) {
                int nb = kb * 2 + (q >> 1);
                uint32_t pl;
                Ph[kb][q] = split2(s[nb][(q & 1) * 2], s[nb][(q & 1) * 2 + 1], pl);
                Pl[kb][q] = pl;
            }
        }

        #pragma unroll
        for (int kb = 0; kb < 12; kb++) {
            int krow = 64 + (kb & 3) * 16;
            int vcol = (kb < 8) ? 0 : 64;
            const uint32_t* af = (kb < 4) ? Ph[kb] : ((kb < 8) ? Pl[kb - 4] : Ph[kb - 8]);
            #pragma unroll
            for (int nbp = 0; nbp < 4; nbp++) {
                uint32_t r0, r1, r2, r3;
                uint32_t addr = smb +
                    (uint32_t)((krow + (lane & 15)) * FROW + vcol + nbp * 16 + (lane >> 4) * 8) * 2;
                ldsm_x4t(r0, r1, r2, r3, addr);
                mma16816(o[nbp * 2],     af, r0, r1);
                mma16816(o[nbp * 2 + 1], af, r2, r3);
            }
        }
        __syncthreads();
    }

    l0 += __shfl_xor_sync(0xffffffffu, l0, 1);
    l0 += __shfl_xor_sync(0xffffffffu, l0, 2);
    l1 += __shfl_xor_sync(0xffffffffu, l1, 1);
    l1 += __shfl_xor_sync(0xffffffffu, l1, 2);
    float inv0 = 1.f / l0, inv1 = 1.f / l1;

    float2 vr0[8], vr1[8];
    float sov0 = 0.f, svv0 = 0.f, sov1 = 0.f, svv1 = 0.f;
    const float* vb = qkv + base + 2 * C_ + h * D_;
    #pragma unroll
    for (int nb = 0; nb < 8; nb++) {
        int d = nb * 8 + (lane & 3) * 2;
        vr0[nb] = *(const float2*)(vb + (size_t)qrow_g0 * C3_ + d);
        vr1[nb] = *(const float2*)(vb + (size_t)(qrow_g0 + 8) * C3_ + d);
        o[nb][0] *= inv0; o[nb][1] *= inv0; o[nb][2] *= inv1; o[nb][3] *= inv1;
        sov0 += o[nb][0] * vr0[nb].x + o[nb][1] * vr0[nb].y;
        svv0 += vr0[nb].x * vr0[nb].x + vr0[nb].y * vr0[nb].y;
        sov1 += o[nb][2] * vr1[nb].x + o[nb][3] * vr1[nb].y;
        svv1 += vr1[nb].x * vr1[nb].x + vr1[nb].y * vr1[nb].y;
    }
    sov0 += __shfl_xor_sync(0xffffffffu, sov0, 1);
    sov0 += __shfl_xor_sync(0xffffffffu, sov0, 2);
    svv0 += __shfl_xor_sync(0xffffffffu, svv0, 1);
    svv0 += __shfl_xor_sync(0xffffffffu, svv0, 2);
    sov1 += __shfl_xor_sync(0xffffffffu, sov1, 1);
    sov1 += __shfl_xor_sync(0xffffffffu, sov1, 2);
    svv1 += __shfl_xor_sync(0xffffffffu, svv1, 1);
    svv1 += __shfl_xor_sync(0xffffffffu, svv1, 2);

    float mx0 = fmaxf(sqrtf(svv0), 1e-12f);
    float mx1 = fmaxf(sqrtf(svv1), 1e-12f);
    float c0 = sov0 / (mx0 * mx0), c1 = sov1 / (mx1 * mx1);

    __nv_bfloat16* a0 = A3out + (size_t)(b * T_ + qrow_g0) * K3_;
    __nv_bfloat16* a1 = a0 + 8 * K3_;
    #pragma unroll
    for (int nb = 0; nb < 8; nb++) {
        int k = h * D_ + nb * 8 + (lane & 3) * 2;
        float y00 = o[nb][0] - c0 * vr0[nb].x, y01 = o[nb][1] - c0 * vr0[nb].y;
        float y10 = o[nb][2] - c1 * vr1[nb].x, y11 = o[nb][3] - c1 * vr1[nb].y;
        uint32_t lo0; uint32_t hi0 = split2(y00, y01, lo0);
        uint32_t lo1; uint32_t hi1 = split2(y10, y11, lo1);
        *(uint32_t*)(a0 + k)        = hi0;
        *(uint32_t*)(a0 + 1024 + k) = lo0;
        *(uint32_t*)(a0 + 2048 + k) = hi0;
        *(uint32_t*)(a1 + k)        = hi1;
        *(uint32_t*)(a1 + 1024 + k) = lo1;
        *(uint32_t*)(a1 + 2048 + k) = hi1;
    }
}

// ---------------------------------------------------------------------------
extern "C" void kernel_launch(void* const* d_in, const int* in_sizes, int n_in,
                              void* d_out, int out_size)
{
    const float* x  = (const float*)d_in[0];
    const float* Wa = (const float*)d_in[1];
    const float* ba = (const float*)d_in[2];
    const float* Wp = (const float*)d_in[3];
    const float* bp = (const float*)d_in[4];
    float* out = (float*)d_out;

    float* qkv;
    __nv_bfloat16 *A3, *B3, *Kp, *Vp;
    cudaGetSymbolAddress((void**)&qkv, g_qkv);
    cudaGetSymbolAddress((void**)&A3,  g_A3);
    cudaGetSymbolAddress((void**)&B3,  g_B3);
    cudaGetSymbolAddress((void**)&Kp,  g_K);
    cudaGetSymbolAddress((void**)&Vp,  g_V);

    const int M = B_ * T_;
    const int flash_smem = 2 * FBUF * 2;        // 69.6 KB
    const int gemm_smem  = NSTG * STGBYTES;     // 162 KB

    static int attr_set = 0;
    if (!attr_set) {
        cudaFuncSetAttribute(flash_hmma, cudaFuncAttributeMaxDynamicSharedMemorySize, flash_smem);
        cudaFuncSetAttribute(hmma_gemm,  cudaFuncAttributeMaxDynamicSharedMemorySize, gemm_smem);
        attr_set = 1;
    }

    prep_W<<<dim3(C3_ / 32, C_ / 32), 256>>>(Wa, B3, C3_);
    split_A<<<(M * C_) / (256 * 8), 256>>>(x, A3);
    hmma_gemm<<<dim3(C3_ / 128, M / 256), 256, gemm_smem>>>(A3, B3, ba, qkv, M, C3_, K3_);

    sparsemax_kv<<<(M * H_) / 8, 256>>>(qkv, Kp, Vp);

    flash_hmma<<<dim3(T_ / 128, H_, B_), 256, flash_smem>>>(qkv, Kp, Vp, A3);

    prep_W<<<dim3(C_ / 32, C_ / 32), 256>>>(Wp, B3, C_);
    hmma_gemm<<<dim3(C_ / 128, M / 256), 256, gemm_smem>>>(A3, B3, bp, out, M, C_, K3_);
}

// round 11
// speedup vs baseline: 1.6240x; 1.6240x over previous
#include <cuda_runtime.h>
#include <cuda_bf16.h>
#include <math.h>
#include <stdint.h>

#define B_  4
#define T_  2048
#define C_  1024
#define H_  16
#define D_  64
#define C3_ 3072
#define K3_ 3072

typedef unsigned long long u64;

__device__ float g_qkv[(size_t)B_ * T_ * C3_];
__device__ __nv_bfloat16 g_A3[(size_t)B_ * T_ * K3_];
__device__ __nv_bfloat16 g_B3[(size_t)C3_ * K3_];
__device__ __nv_bfloat16 g_K[(size_t)B_ * H_ * T_ * 128];
__device__ __nv_bfloat16 g_V[(size_t)B_ * H_ * T_ * 128];

// ---- helpers ----
__device__ __forceinline__ uint32_t smem_u32(const void* p) {
    uint32_t a;
    asm("{ .reg .u64 t; cvta.to.shared.u64 t, %1; cvt.u32.u64 %0, t; }" : "=r"(a) : "l"(p));
    return a;
}
__device__ __forceinline__ void cp16(uint32_t dst, const void* src) {
    asm volatile("cp.async.cg.shared.global [%0], [%1], 16;" :: "r"(dst), "l"(src));
}
__device__ __forceinline__ void ldsm_x4(uint32_t& r0, uint32_t& r1, uint32_t& r2, uint32_t& r3,
                                        uint32_t addr) {
    asm volatile("ldmatrix.sync.aligned.m8n8.x4.shared.b16 {%0,%1,%2,%3},[%4];"
                 : "=r"(r0), "=r"(r1), "=r"(r2), "=r"(r3) : "r"(addr));
}
__device__ __forceinline__ void ldsm_x4t(uint32_t& r0, uint32_t& r1, uint32_t& r2, uint32_t& r3,
                                         uint32_t addr) {
    asm volatile("ldmatrix.sync.aligned.m8n8.x4.trans.shared.b16 {%0,%1,%2,%3},[%4];"
                 : "=r"(r0), "=r"(r1), "=r"(r2), "=r"(r3) : "r"(addr));
}
__device__ __forceinline__ void mma16816(float* c, const uint32_t* a, uint32_t b0, uint32_t b1) {
    asm volatile(
        "mma.sync.aligned.m16n8k16.row.col.f32.bf16.bf16.f32 "
        "{%0,%1,%2,%3},{%4,%5,%6,%7},{%8,%9},{%0,%1,%2,%3};"
        : "+f"(c[0]), "+f"(c[1]), "+f"(c[2]), "+f"(c[3])
        : "r"(a[0]), "r"(a[1]), "r"(a[2]), "r"(a[3]), "r"(b0), "r"(b1));
}
__device__ __forceinline__ uint32_t pkbf(float lo, float hi) {
    uint32_t r; asm("cvt.rn.bf16x2.f32 %0,%1,%2;" : "=r"(r) : "f"(hi), "f"(lo)); return r;
}
__device__ __forceinline__ uint32_t split2(float a, float b, uint32_t& lo) {
    uint32_t hp = pkbf(a, b);
    float la = a - __uint_as_float(hp << 16);
    float lb = b - __uint_as_float(hp & 0xFFFF0000u);
    lo = pkbf(la, lb);
    return hp;
}
__device__ __forceinline__ uint2 split4(float4 f, uint2& lo) {
    uint32_t l0, l1;
    uint32_t h0 = split2(f.x, f.y, l0);
    uint32_t h1 = split2(f.z, f.w, l1);
    lo = make_uint2(l0, l1);
    return make_uint2(h0, h1);
}

// ---------------------------------------------------------------------------
// split_A: src fp32 [M,1024] -> dst bf16 [M,3072] = [hi|lo|hi]
// ---------------------------------------------------------------------------
__global__ __launch_bounds__(256) void split_A(
    const float* __restrict__ src, __nv_bfloat16* __restrict__ dst)
{
    size_t idx = ((size_t)blockIdx.x * 256 + threadIdx.x) * 8;
    int m = (int)(idx >> 10), k = (int)(idx & 1023);
    float4 f0 = *(const float4*)(src + idx);
    float4 f1 = *(const float4*)(src + idx + 4);
    uint2 l0, l1;
    uint2 h0 = split4(f0, l0);
    uint2 h1 = split4(f1, l1);
    __nv_bfloat16* r = dst + (size_t)m * K3_;
    *(uint4*)(r + k)        = make_uint4(h0.x, h0.y, h1.x, h1.y);
    *(uint4*)(r + 1024 + k) = make_uint4(l0.x, l0.y, l1.x, l1.y);
    *(uint4*)(r + 2048 + k) = make_uint4(h0.x, h0.y, h1.x, h1.y);
}

// ---------------------------------------------------------------------------
// prep_W: W fp32 [1024, N] -> Bo bf16 [N,3072] = [hi|hi|lo]
// ---------------------------------------------------------------------------
__global__ __launch_bounds__(256) void prep_W(
    const float* __restrict__ W, __nv_bfloat16* __restrict__ Bo, int N)
{
    __shared__ float t[32][33];
    int n0 = blockIdx.x * 32, k0 = blockIdx.y * 32;
    {
        int tx = threadIdx.x & 31, ty = threadIdx.x >> 5;
        #pragma unroll
        for (int i = 0; i < 4; i++)
            t[ty + i * 8][tx] = W[(size_t)(k0 + ty + i * 8) * N + n0 + tx];
    }
    __syncthreads();
    int kk = (threadIdx.x & 15) * 2, ny = threadIdx.x >> 4;
    #pragma unroll
    for (int i = 0; i < 2; i++) {
        int n = ny + i * 16;
        uint32_t lp;
        uint32_t hp = split2(t[kk][n], t[kk + 1][n], lp);
        size_t r = (size_t)(n0 + n) * K3_;
        *(uint32_t*)(Bo + r + k0 + kk)        = hp;
        *(uint32_t*)(Bo + r + 1024 + k0 + kk) = hp;
        *(uint32_t*)(Bo + r + 2048 + k0 + kk) = lp;
    }
}

// ---------------------------------------------------------------------------
// HMMA GEMM: 128x128 CTA tile, BK=64, 3-stage cp.async pipeline.
// __launch_bounds__(256,2): cap regs at 128 so 2 CTAs co-reside per SM
// (2 x 110.6KB smem = 221.2KB fits the 228KB SM budget) -> cross-CTA overlap
// of sync/ldsm bubbles.
// ---------------------------------------------------------------------------
#define BK    64
#define ROWE  72     // 64 data + 8 pad (144B stride, conflict-free ldmatrix)
#define NSTG  3
#define OPBYTES (128 * ROWE * 2)

__global__ __launch_bounds__(256, 2) void hmma_gemm(
    const __nv_bfloat16* __restrict__ A, const __nv_bfloat16* __restrict__ Bk,
    const float* __restrict__ bias, float* __restrict__ Cout,
    int M, int N, int K)
{
    extern __shared__ __align__(16) __nv_bfloat16 gsm[];

    const int tid  = threadIdx.x;
    const int lane = tid & 31;
    const int wid  = tid >> 5;
    const int wm   = wid >> 2;
    const int wn   = wid & 3;
    const int m0 = blockIdx.y * 128, n0 = blockIdx.x * 128;

    const uint32_t smb = smem_u32(gsm);

    auto load_tile = [&](int stg, int kt) {
        const __nv_bfloat16* Ag = A + (size_t)m0 * K + kt * BK;
        const __nv_bfloat16* Bg = Bk + (size_t)n0 * K + kt * BK;
        uint32_t sA = smb + stg * (2 * OPBYTES);
        uint32_t sB = sA + OPBYTES;
        #pragma unroll
        for (int it = 0; it < 4; it++) {
            int c = tid + it * 256;            // 0..1023
            int row = c >> 3, seg = c & 7;
            uint32_t doff = (uint32_t)(row * ROWE + seg * 8) * 2;
            cp16(sA + doff, Ag + (size_t)row * K + seg * 8);
            cp16(sB + doff, Bg + (size_t)row * K + seg * 8);
        }
        asm volatile("cp.async.commit_group;" ::: "memory");
    };

    float acc[4][4][4];
    #pragma unroll
    for (int i = 0; i < 4; i++)
        #pragma unroll
        for (int j = 0; j < 4; j++)
            #pragma unroll
            for (int e = 0; e < 4; e++) acc[i][j][e] = 0.f;

    const int nkt = K / BK;   // 48
    load_tile(0, 0);
    load_tile(1, 1);

    const int a_row = wm * 64 + (lane & 15);
    const int a_ko  = (lane >> 4) * 8;
    const int b_row = wn * 32 + (lane & 7) + ((lane >> 4) & 1) * 8;
    const int b_ko  = ((lane >> 3) & 1) * 8;

    int stg = 0;
    for (int kt = 0; kt < nkt; kt++) {
        if (kt + 2 < nkt) {
            int s2 = stg + 2; if (s2 >= NSTG) s2 -= NSTG;
            load_tile(s2, kt + 2);
        } else {
            asm volatile("cp.async.commit_group;" ::: "memory");
        }
        asm volatile("cp.async.wait_group 2;" ::: "memory");
        __syncthreads();

        const uint32_t aT = smb + stg * (2 * OPBYTES);
        const uint32_t bT = aT + OPBYTES;

        #pragma unroll
        for (int ks = 0; ks < 4; ks++) {
            uint32_t af[4][4];
            #pragma unroll
            for (int mi = 0; mi < 4; mi++)
                ldsm_x4(af[mi][0], af[mi][1], af[mi][2], af[mi][3],
                        aT + (uint32_t)((a_row + mi * 16) * ROWE + ks * 16 + a_ko) * 2);
            uint32_t bf[4][2];
            #pragma unroll
            for (int nb = 0; nb < 2; nb++) {
                uint32_t r0, r1, r2, r3;
                ldsm_x4(r0, r1, r2, r3,
                        bT + (uint32_t)((b_row + nb * 16) * ROWE + ks * 16 + b_ko) * 2);
                bf[nb * 2][0] = r0; bf[nb * 2][1] = r1;
                bf[nb * 2 + 1][0] = r2; bf[nb * 2 + 1][1] = r3;
            }
            #pragma unroll
            for (int mi = 0; mi < 4; mi++)
                #pragma unroll
                for (int ni = 0; ni < 4; ni++)
                    mma16816(acc[mi][ni], af[mi], bf[ni][0], bf[ni][1]);
        }
        __syncthreads();
        if (++stg >= NSTG) stg = 0;
    }

    #pragma unroll
    for (int mi = 0; mi < 4; mi++) {
        int row_g = m0 + wm * 64 + mi * 16 + (lane >> 2);
        #pragma unroll
        for (int ni = 0; ni < 4; ni++) {
            int col_g = n0 + wn * 32 + ni * 8 + (lane & 3) * 2;
            float b0 = bias[col_g], b1 = bias[col_g + 1];
            float2 o0 = make_float2(acc[mi][ni][0] + b0, acc[mi][ni][1] + b1);
            float2 o1 = make_float2(acc[mi][ni][2] + b0, acc[mi][ni][3] + b1);
            *(float2*)(Cout + (size_t)row_g * N + col_g) = o0;
            *(float2*)(Cout + (size_t)(row_g + 8) * N + col_g) = o1;
        }
    }
}

// ---------------------------------------------------------------------------
// Sparsemax over K head-dim + fused split of K AND V into bf16 [hi|lo] rows.
// ---------------------------------------------------------------------------
__global__ __launch_bounds__(256) void sparsemax_kv(
    const float* __restrict__ qkv,
    __nv_bfloat16* __restrict__ Ko, __nv_bfloat16* __restrict__ Vo)
{
    const int lane = threadIdx.x & 31;
    const int wrp  = threadIdx.x >> 5;
    const size_t row = (size_t)blockIdx.x * 8 + wrp;
    const size_t bt  = row >> 4;
    const int    h   = (int)(row & 15);
    const int    b   = (int)(bt >> 11);
    const int    t   = (int)(bt & 2047);

    const float* pk = qkv + bt * C3_ + C_ + h * D_;
    float2 z = *(const float2*)(pk + 2 * lane);
    float v0 = z.x, v1 = z.y;

    #pragma unroll
    for (int k = 2; k <= 64; k <<= 1) {
        #pragma unroll
        for (int j = k >> 1; j > 0; j >>= 1) {
            if (j < 32) {
                float p0 = __shfl_xor_sync(0xffffffffu, v0, j);
                float p1 = __shfl_xor_sync(0xffffffffu, v1, j);
                bool lower = (lane & j) == 0;
                bool up0 = (lane & k) != 0;
                bool up1 = ((lane + 32) & k) != 0;
                v0 = (lower == up0) ? fminf(v0, p0) : fmaxf(v0, p0);
                v1 = (lower == up1) ? fminf(v1, p1) : fmaxf(v1, p1);
            } else {
                float a = fmaxf(v0, v1), bmin = fminf(v0, v1);
                v0 = a; v1 = bmin;
            }
        }
    }

    float c0 = v0;
    #pragma unroll
    for (int o = 1; o < 32; o <<= 1) {
        float tt = __shfl_up_sync(0xffffffffu, c0, o);
        if (lane >= o) c0 += tt;
    }
    float c1 = v1;
    #pragma unroll
    for (int o = 1; o < 32; o <<= 1) {
        float tt = __shfl_up_sync(0xffffffffu, c1, o);
        if (lane >= o) c1 += tt;
    }
    c1 += __shfl_sync(0xffffffffu, c0, 31);

    bool s0 = 1.f + (float)(lane + 1)  * v0 > c0;
    bool s1 = 1.f + (float)(lane + 33) * v1 > c1;
    int rho = __popc(__ballot_sync(0xffffffffu, s0)) +
              __popc(__ballot_sync(0xffffffffu, s1));
    int ridx = rho - 1;
    float csA = __shfl_sync(0xffffffffu, c0, ridx & 31);
    float csB = __shfl_sync(0xffffffffu, c1, ridx & 31);
    float cs  = (ridx < 32) ? csA : csB;
    float tau = (cs - 1.f) / (float)rho;

    float k0 = fmaxf(z.x - tau, 0.f), k1 = fmaxf(z.y - tau, 0.f);
    uint32_t klo; uint32_t khi = split2(k0, k1, klo);
    __nv_bfloat16* kr = Ko + ((size_t)(b * H_ + h) * T_ + t) * 128;
    *(uint32_t*)(kr + 2 * lane)      = khi;
    *(uint32_t*)(kr + 64 + 2 * lane) = klo;

    float2 vv = *(const float2*)(pk + C_ + 2 * lane);
    uint32_t vlo; uint32_t vhi = split2(vv.x, vv.y, vlo);
    __nv_bfloat16* vr = Vo + ((size_t)(b * H_ + h) * T_ + t) * 128;
    *(uint32_t*)(vr + 2 * lane)      = vhi;
    *(uint32_t*)(vr + 64 + 2 * lane) = vlo;
}

// ---------------------------------------------------------------------------
// Flash attention (LPT ordering), cp.async K/V, fused XSA, split-A3 epilogue.
// ---------------------------------------------------------------------------
#define FROW 136
#define FBUF (128 * FROW)

__global__ __launch_bounds__(256) void flash_hmma(
    const float* __restrict__ qkv,
    const __nv_bfloat16* __restrict__ Ks, const __nv_bfloat16* __restrict__ Vs,
    __nv_bfloat16* __restrict__ A3out)
{
    extern __shared__ __align__(16) __nv_bfloat16 smx[];

    const int tid  = threadIdx.x;
    const int lane = tid & 31;
    const int w    = tid >> 5;
    const int qt = (int)gridDim.x - 1 - (int)blockIdx.x;
    const int h = blockIdx.y, b = blockIdx.z;
    const size_t base = (size_t)b * T_ * C3_;

    const __nv_bfloat16* Kb = Ks + (size_t)(b * H_ + h) * T_ * 128;
    const __nv_bfloat16* Vb = Vs + (size_t)(b * H_ + h) * T_ * 128;
    const uint32_t smb0 = smem_u32(smx);

    auto load_tile = [&](int buf, int kt) {
        const __nv_bfloat16* kg = Kb + (size_t)kt * 64 * 128;
        const __nv_bfloat16* vg = Vb + (size_t)kt * 64 * 128;
        uint32_t sb = smb0 + buf * (FBUF * 2);
        #pragma unroll
        for (int it = 0; it < 4; it++) {
            int c = tid + it * 256;
            int j = c >> 4, seg = c & 15;
            cp16(sb + (uint32_t)(j * FROW) * 2 + seg * 16,        kg + j * 128 + seg * 8);
            cp16(sb + (uint32_t)((64 + j) * FROW) * 2 + seg * 16, vg + j * 128 + seg * 8);
        }
        asm volatile("cp.async.commit_group;" ::: "memory");
    };

    load_tile(0, 0);
    {
        __nv_bfloat16* qb = smx + FBUF;
        for (int i = tid; i < 2048; i += 256) {
            int row = i >> 4, d = (i & 15) * 4;
            float4 f4 = *(const float4*)(qkv + base + (size_t)(qt * 128 + row) * C3_ + h * D_ + d);
            f4.x *= 0.125f; f4.y *= 0.125f; f4.z *= 0.125f; f4.w *= 0.125f;
            uint2 lo; uint2 hi = split4(f4, lo);
            *(uint2*)&qb[row * FROW + d]      = hi;
            *(uint2*)&qb[row * FROW + 64 + d] = lo;
        }
    }
    __syncthreads();

    uint32_t qf[8][4];
    #pragma unroll
    for (int kb = 0; kb < 8; kb++) {
        uint32_t addr = smb0 + FBUF * 2 +
                        (uint32_t)((w * 16 + (lane & 15)) * FROW + kb * 16 + (lane >> 4) * 8) * 2;
        ldsm_x4(qf[kb][0], qf[kb][1], qf[kb][2], qf[kb][3], addr);
    }
    __syncthreads();

    float o[8][4];
    #pragma unroll
    for (int nb = 0; nb < 8; nb++)
        #pragma unroll
        for (int e = 0; e < 4; e++) o[nb][e] = 0.f;
    float m0 = -1e30f, m1 = -1e30f, l0 = 0.f, l1 = 0.f;

    const int qrow_g0 = qt * 128 + w * 16 + (lane >> 2);
    const int nkt = (qt + 1) * 2;

    for (int kt = 0; kt < nkt; kt++) {
        if (kt + 1 < nkt) load_tile((kt + 1) & 1, kt + 1);
        else asm volatile("cp.async.commit_group;" ::: "memory");
        asm volatile("cp.async.wait_group 1;" ::: "memory");
        __syncthreads();

        const uint32_t smb = smb0 + (kt & 1) * (FBUF * 2);

        float s[8][4];
        #pragma unroll
        for (int nb = 0; nb < 8; nb++)
            #pragma unroll
            for (int e = 0; e < 4; e++) s[nb][e] = 0.f;

        #pragma unroll
        for (int kb = 0; kb < 12; kb++) {
            int bcol = (kb < 4) ? kb * 16 : ((kb < 8) ? (kb - 4) * 16 : 64 + (kb - 8) * 16);
            const uint32_t* af = (kb < 8) ? qf[kb] : qf[kb - 8];
            #pragma unroll
            for (int nbp = 0; nbp < 4; nbp++) {
                uint32_t r0, r1, r2, r3;
                uint32_t addr = smb +
                    (uint32_t)((nbp * 16 + (lane & 7) + ((lane >> 4) & 1) * 8) * FROW
                               + bcol + ((lane >> 3) & 1) * 8) * 2;
                ldsm_x4(r0, r1, r2, r3, addr);
                mma16816(s[nbp * 2],     af, r0, r1);
                mma16816(s[nbp * 2 + 1], af, r2, r3);
            }
        }

        if (kt * 64 + 63 > qt * 128 + w * 16) {
            #pragma unroll
            for (int nb = 0; nb < 8; nb++) {
                int col = kt * 64 + nb * 8 + (lane & 3) * 2;
                if (col     > qrow_g0)     s[nb][0] = -1e30f;
                if (col + 1 > qrow_g0)     s[nb][1] = -1e30f;
                if (col     > qrow_g0 + 8) s[nb][2] = -1e30f;
                if (col + 1 > qrow_g0 + 8) s[nb][3] = -1e30f;
            }
        }

        float tm0 = -1e30f, tm1 = -1e30f;
        #pragma unroll
        for (int nb = 0; nb < 8; nb++) {
            tm0 = fmaxf(tm0, fmaxf(s[nb][0], s[nb][1]));
            tm1 = fmaxf(tm1, fmaxf(s[nb][2], s[nb][3]));
        }
        tm0 = fmaxf(tm0, __shfl_xor_sync(0xffffffffu, tm0, 1));
        tm0 = fmaxf(tm0, __shfl_xor_sync(0xffffffffu, tm0, 2));
        tm1 = fmaxf(tm1, __shfl_xor_sync(0xffffffffu, tm1, 1));
        tm1 = fmaxf(tm1, __shfl_xor_sync(0xffffffffu, tm1, 2));

        float m0n = fmaxf(m0, tm0), m1n = fmaxf(m1, tm1);
        float corr0 = __expf(m0 - m0n), corr1 = __expf(m1 - m1n);
        m0 = m0n; m1 = m1n;
        l0 *= corr0; l1 *= corr1;

        #pragma unroll
        for (int nb = 0; nb < 8; nb++) {
            s[nb][0] = __expf(s[nb][0] - m0);
            s[nb][1] = __expf(s[nb][1] - m0);
            s[nb][2] = __expf(s[nb][2] - m1);
            s[nb][3] = __expf(s[nb][3] - m1);
            l0 += s[nb][0] + s[nb][1];
            l1 += s[nb][2] + s[nb][3];
            o[nb][0] *= corr0; o[nb][1] *= corr0;
            o[nb][2] *= corr1; o[nb][3] *= corr1;
        }

        uint32_t Ph[4][4], Pl[4][4];
        #pragma unroll
        for (int kb = 0; kb < 4; kb++) {
            #pragma unroll
            for (int q = 0; q < 4; q++) {
                int nb = kb * 2 + (q >> 1);
                uint32_t pl;
                Ph[kb][q] = split2(s[nb][(q & 1) * 2], s[nb][(q & 1) * 2 + 1], pl);
                Pl[kb][q] = pl;
            }
        }

        #pragma unroll
        for (int kb = 0; kb < 12; kb++) {
            int krow = 64 + (kb & 3) * 16;
            int vcol = (kb < 8) ? 0 : 64;
            const uint32_t* af = (kb < 4) ? Ph[kb] : ((kb < 8) ? Pl[kb - 4] : Ph[kb - 8]);
            #pragma unroll
            for (int nbp = 0; nbp < 4; nbp++) {
                uint32_t r0, r1, r2, r3;
                uint32_t addr = smb +
                    (uint32_t)((krow + (lane & 15)) * FROW + vcol + nbp * 16 + (lane >> 4) * 8) * 2;
                ldsm_x4t(r0, r1, r2, r3, addr);
                mma16816(o[nbp * 2],     af, r0, r1);
                mma16816(o[nbp * 2 + 1], af, r2, r3);
            }
        }
        __syncthreads();
    }

    l0 += __shfl_xor_sync(0xffffffffu, l0, 1);
    l0 += __shfl_xor_sync(0xffffffffu, l0, 2);
    l1 += __shfl_xor_sync(0xffffffffu, l1, 1);
    l1 += __shfl_xor_sync(0xffffffffu, l1, 2);
    float inv0 = 1.f / l0, inv1 = 1.f / l1;

    float2 vr0[8], vr1[8];
    float sov0 = 0.f, svv0 = 0.f, sov1 = 0.f, svv1 = 0.f;
    const float* vb = qkv + base + 2 * C_ + h * D_;
    #pragma unroll
    for (int nb = 0; nb < 8; nb++) {
        int d = nb * 8 + (lane & 3) * 2;
        vr0[nb] = *(const float2*)(vb + (size_t)qrow_g0 * C3_ + d);
        vr1[nb] = *(const float2*)(vb + (size_t)(qrow_g0 + 8) * C3_ + d);
        o[nb][0] *= inv0; o[nb][1] *= inv0; o[nb][2] *= inv1; o[nb][3] *= inv1;
        sov0 += o[nb][0] * vr0[nb].x + o[nb][1] * vr0[nb].y;
        svv0 += vr0[nb].x * vr0[nb].x + vr0[nb].y * vr0[nb].y;
        sov1 += o[nb][2] * vr1[nb].x + o[nb][3] * vr1[nb].y;
        svv1 += vr1[nb].x * vr1[nb].x + vr1[nb].y * vr1[nb].y;
    }
    sov0 += __shfl_xor_sync(0xffffffffu, sov0, 1);
    sov0 += __shfl_xor_sync(0xffffffffu, sov0, 2);
    svv0 += __shfl_xor_sync(0xffffffffu, svv0, 1);
    svv0 += __shfl_xor_sync(0xffffffffu, svv0, 2);
    sov1 += __shfl_xor_sync(0xffffffffu, sov1, 1);
    sov1 += __shfl_xor_sync(0xffffffffu, sov1, 2);
    svv1 += __shfl_xor_sync(0xffffffffu, svv1, 1);
    svv1 += __shfl_xor_sync(0xffffffffu, svv1, 2);

    float mx0 = fmaxf(sqrtf(svv0), 1e-12f);
    float mx1 = fmaxf(sqrtf(svv1), 1e-12f);
    float c0 = sov0 / (mx0 * mx0), c1 = sov1 / (mx1 * mx1);

    __nv_bfloat16* a0 = A3out + (size_t)(b * T_ + qrow_g0) * K3_;
    __nv_bfloat16* a1 = a0 + 8 * K3_;
    #pragma unroll
    for (int nb = 0; nb < 8; nb++) {
        int k = h * D_ + nb * 8 + (lane & 3) * 2;
        float y00 = o[nb][0] - c0 * vr0[nb].x, y01 = o[nb][1] - c0 * vr0[nb].y;
        float y10 = o[nb][2] - c1 * vr1[nb].x, y11 = o[nb][3] - c1 * vr1[nb].y;
        uint32_t lo0; uint32_t hi0 = split2(y00, y01, lo0);
        uint32_t lo1; uint32_t hi1 = split2(y10, y11, lo1);
        *(uint32_t*)(a0 + k)        = hi0;
        *(uint32_t*)(a0 + 1024 + k) = lo0;
        *(uint32_t*)(a0 + 2048 + k) = hi0;
        *(uint32_t*)(a1 + k)        = hi1;
        *(uint32_t*)(a1 + 1024 + k) = lo1;
        *(uint32_t*)(a1 + 2048 + k) = hi1;
    }
}

// ---------------------------------------------------------------------------
extern "C" void kernel_launch(void* const* d_in, const int* in_sizes, int n_in,
                              void* d_out, int out_size)
{
    const float* x  = (const float*)d_in[0];
    const float* Wa = (const float*)d_in[1];
    const float* ba = (const float*)d_in[2];
    const float* Wp = (const float*)d_in[3];
    const float* bp = (const float*)d_in[4];
    float* out = (float*)d_out;

    float* qkv;
    __nv_bfloat16 *A3, *B3, *Kp, *Vp;
    cudaGetSymbolAddress((void**)&qkv, g_qkv);
    cudaGetSymbolAddress((void**)&A3,  g_A3);
    cudaGetSymbolAddress((void**)&B3,  g_B3);
    cudaGetSymbolAddress((void**)&Kp,  g_K);
    cudaGetSymbolAddress((void**)&Vp,  g_V);

    const int M = B_ * T_;
    const int flash_smem = 2 * FBUF * 2;            // 69.6 KB
    const int gemm_smem  = NSTG * 2 * OPBYTES;      // 110.6 KB

    static int attr_set = 0;
    if (!attr_set) {
        cudaFuncSetAttribute(flash_hmma, cudaFuncAttributeMaxDynamicSharedMemorySize, flash_smem);
        cudaFuncSetAttribute(hmma_gemm,  cudaFuncAttributeMaxDynamicSharedMemorySize, gemm_smem);
        attr_set = 1;
    }

    prep_W<<<dim3(C3_ / 32, C_ / 32), 256>>>(Wa, B3, C3_);
    split_A<<<(M * C_) / (256 * 8), 256>>>(x, A3);
    hmma_gemm<<<dim3(C3_ / 128, M / 128), 256, gemm_smem>>>(A3, B3, ba, qkv, M, C3_, K3_);

    sparsemax_kv<<<(M * H_) / 8, 256>>>(qkv, Kp, Vp);

    flash_hmma<<<dim3(T_ / 128, H_, B_), 256, flash_smem>>>(qkv, Kp, Vp, A3);

    prep_W<<<dim3(C_ / 32, C_ / 32), 256>>>(Wp, B3, C_);
    hmma_gemm<<<dim3(C_ / 128, M / 128), 256, gemm_smem>>>(A3, B3, bp, out, M, C_, K3_);
}

// round 12
// speedup vs baseline: 1.6877x; 1.0392x over previous
#include <cuda_runtime.h>
#include <cuda_bf16.h>
#include <math.h>
#include <stdint.h>

#define B_  4
#define T_  2048
#define C_  1024
#define H_  16
#define D_  64
#define C3_ 3072
#define K3_ 3072

typedef unsigned long long u64;

__device__ float g_qkv[(size_t)B_ * T_ * C3_];
__device__ __nv_bfloat16 g_A3[(size_t)B_ * T_ * K3_];
__device__ __nv_bfloat16 g_B3[(size_t)C3_ * K3_];
__device__ __nv_bfloat16 g_K[(size_t)B_ * H_ * T_ * 128];
__device__ __nv_bfloat16 g_V[(size_t)B_ * H_ * T_ * 128];

// ---- helpers ----
__device__ __forceinline__ uint32_t smem_u32(const void* p) {
    uint32_t a;
    asm("{ .reg .u64 t; cvta.to.shared.u64 t, %1; cvt.u32.u64 %0, t; }" : "=r"(a) : "l"(p));
    return a;
}
__device__ __forceinline__ void cp16(uint32_t dst, const void* src) {
    asm volatile("cp.async.cg.shared.global [%0], [%1], 16;" :: "r"(dst), "l"(src));
}
__device__ __forceinline__ void ldsm_x4(uint32_t& r0, uint32_t& r1, uint32_t& r2, uint32_t& r3,
                                        uint32_t addr) {
    asm volatile("ldmatrix.sync.aligned.m8n8.x4.shared.b16 {%0,%1,%2,%3},[%4];"
                 : "=r"(r0), "=r"(r1), "=r"(r2), "=r"(r3) : "r"(addr));
}
__device__ __forceinline__ void ldsm_x4t(uint32_t& r0, uint32_t& r1, uint32_t& r2, uint32_t& r3,
                                         uint32_t addr) {
    asm volatile("ldmatrix.sync.aligned.m8n8.x4.trans.shared.b16 {%0,%1,%2,%3},[%4];"
                 : "=r"(r0), "=r"(r1), "=r"(r2), "=r"(r3) : "r"(addr));
}
__device__ __forceinline__ void mma16816(float* c, const uint32_t* a, uint32_t b0, uint32_t b1) {
    asm volatile(
        "mma.sync.aligned.m16n8k16.row.col.f32.bf16.bf16.f32 "
        "{%0,%1,%2,%3},{%4,%5,%6,%7},{%8,%9},{%0,%1,%2,%3};"
        : "+f"(c[0]), "+f"(c[1]), "+f"(c[2]), "+f"(c[3])
        : "r"(a[0]), "r"(a[1]), "r"(a[2]), "r"(a[3]), "r"(b0), "r"(b1));
}
__device__ __forceinline__ uint32_t pkbf(float lo, float hi) {
    uint32_t r; asm("cvt.rn.bf16x2.f32 %0,%1,%2;" : "=r"(r) : "f"(hi), "f"(lo)); return r;
}
__device__ __forceinline__ uint32_t split2(float a, float b, uint32_t& lo) {
    uint32_t hp = pkbf(a, b);
    float la = a - __uint_as_float(hp << 16);
    float lb = b - __uint_as_float(hp & 0xFFFF0000u);
    lo = pkbf(la, lb);
    return hp;
}
__device__ __forceinline__ uint2 split4(float4 f, uint2& lo) {
    uint32_t l0, l1;
    uint32_t h0 = split2(f.x, f.y, l0);
    uint32_t h1 = split2(f.z, f.w, l1);
    lo = make_uint2(l0, l1);
    return make_uint2(h0, h1);
}

// ---------------------------------------------------------------------------
// split_A: src fp32 [M,1024] -> dst bf16 [M,3072] = [hi|lo|hi]
// ---------------------------------------------------------------------------
__global__ __launch_bounds__(256) void split_A(
    const float* __restrict__ src, __nv_bfloat16* __restrict__ dst)
{
    size_t idx = ((size_t)blockIdx.x * 256 + threadIdx.x) * 8;
    int m = (int)(idx >> 10), k = (int)(idx & 1023);
    float4 f0 = *(const float4*)(src + idx);
    float4 f1 = *(const float4*)(src + idx + 4);
    uint2 l0, l1;
    uint2 h0 = split4(f0, l0);
    uint2 h1 = split4(f1, l1);
    __nv_bfloat16* r = dst + (size_t)m * K3_;
    *(uint4*)(r + k)        = make_uint4(h0.x, h0.y, h1.x, h1.y);
    *(uint4*)(r + 1024 + k) = make_uint4(l0.x, l0.y, l1.x, l1.y);
    *(uint4*)(r + 2048 + k) = make_uint4(h0.x, h0.y, h1.x, h1.y);
}

// ---------------------------------------------------------------------------
// prep_W: W fp32 [1024, N] -> Bo bf16 [N,3072] = [hi|hi|lo]
// ---------------------------------------------------------------------------
__global__ __launch_bounds__(256) void prep_W(
    const float* __restrict__ W, __nv_bfloat16* __restrict__ Bo, int N)
{
    __shared__ float t[32][33];
    int n0 = blockIdx.x * 32, k0 = blockIdx.y * 32;
    {
        int tx = threadIdx.x & 31, ty = threadIdx.x >> 5;
        #pragma unroll
        for (int i = 0; i < 4; i++)
            t[ty + i * 8][tx] = W[(size_t)(k0 + ty + i * 8) * N + n0 + tx];
    }
    __syncthreads();
    int kk = (threadIdx.x & 15) * 2, ny = threadIdx.x >> 4;
    #pragma unroll
    for (int i = 0; i < 2; i++) {
        int n = ny + i * 16;
        uint32_t lp;
        uint32_t hp = split2(t[kk][n], t[kk + 1][n], lp);
        size_t r = (size_t)(n0 + n) * K3_;
        *(uint32_t*)(Bo + r + k0 + kk)        = hp;
        *(uint32_t*)(Bo + r + 1024 + k0 + kk) = hp;
        *(uint32_t*)(Bo + r + 2048 + k0 + kk) = lp;
    }
}

// ---------------------------------------------------------------------------
// HMMA GEMM: exact r8 config (128x128 tile, BK=64, 3-stage, no occ cap).
// ---------------------------------------------------------------------------
#define BK    64
#define ROWE  72
#define NSTG  3
#define OPBYTES (128 * ROWE * 2)

__global__ __launch_bounds__(256) void hmma_gemm(
    const __nv_bfloat16* __restrict__ A, const __nv_bfloat16* __restrict__ Bk,
    const float* __restrict__ bias, float* __restrict__ Cout,
    int M, int N, int K)
{
    extern __shared__ __align__(16) __nv_bfloat16 gsm[];

    const int tid  = threadIdx.x;
    const int lane = tid & 31;
    const int wid  = tid >> 5;
    const int wm   = wid >> 2;
    const int wn   = wid & 3;
    const int m0 = blockIdx.y * 128, n0 = blockIdx.x * 128;

    const uint32_t smb = smem_u32(gsm);

    auto load_tile = [&](int stg, int kt) {
        const __nv_bfloat16* Ag = A + (size_t)m0 * K + kt * BK;
        const __nv_bfloat16* Bg = Bk + (size_t)n0 * K + kt * BK;
        uint32_t sA = smb + stg * (2 * OPBYTES);
        uint32_t sB = sA + OPBYTES;
        #pragma unroll
        for (int it = 0; it < 4; it++) {
            int c = tid + it * 256;
            int row = c >> 3, seg = c & 7;
            uint32_t doff = (uint32_t)(row * ROWE + seg * 8) * 2;
            cp16(sA + doff, Ag + (size_t)row * K + seg * 8);
            cp16(sB + doff, Bg + (size_t)row * K + seg * 8);
        }
        asm volatile("cp.async.commit_group;" ::: "memory");
    };

    float acc[4][4][4];
    #pragma unroll
    for (int i = 0; i < 4; i++)
        #pragma unroll
        for (int j = 0; j < 4; j++)
            #pragma unroll
            for (int e = 0; e < 4; e++) acc[i][j][e] = 0.f;

    const int nkt = K / BK;
    load_tile(0, 0);
    load_tile(1, 1);

    const int a_row = wm * 64 + (lane & 15);
    const int a_ko  = (lane >> 4) * 8;
    const int b_row = wn * 32 + (lane & 7) + ((lane >> 4) & 1) * 8;
    const int b_ko  = ((lane >> 3) & 1) * 8;

    int stg = 0;
    for (int kt = 0; kt < nkt; kt++) {
        if (kt + 2 < nkt) {
            int s2 = stg + 2; if (s2 >= NSTG) s2 -= NSTG;
            load_tile(s2, kt + 2);
        } else {
            asm volatile("cp.async.commit_group;" ::: "memory");
        }
        asm volatile("cp.async.wait_group 2;" ::: "memory");
        __syncthreads();

        const uint32_t aT = smb + stg * (2 * OPBYTES);
        const uint32_t bT = aT + OPBYTES;

        #pragma unroll
        for (int ks = 0; ks < 4; ks++) {
            uint32_t af[4][4];
            #pragma unroll
            for (int mi = 0; mi < 4; mi++)
                ldsm_x4(af[mi][0], af[mi][1], af[mi][2], af[mi][3],
                        aT + (uint32_t)((a_row + mi * 16) * ROWE + ks * 16 + a_ko) * 2);
            uint32_t bf[4][2];
            #pragma unroll
            for (int nb = 0; nb < 2; nb++) {
                uint32_t r0, r1, r2, r3;
                ldsm_x4(r0, r1, r2, r3,
                        bT + (uint32_t)((b_row + nb * 16) * ROWE + ks * 16 + b_ko) * 2);
                bf[nb * 2][0] = r0; bf[nb * 2][1] = r1;
                bf[nb * 2 + 1][0] = r2; bf[nb * 2 + 1][1] = r3;
            }
            #pragma unroll
            for (int mi = 0; mi < 4; mi++)
                #pragma unroll
                for (int ni = 0; ni < 4; ni++)
                    mma16816(acc[mi][ni], af[mi], bf[ni][0], bf[ni][1]);
        }
        __syncthreads();
        if (++stg >= NSTG) stg = 0;
    }

    #pragma unroll
    for (int mi = 0; mi < 4; mi++) {
        int row_g = m0 + wm * 64 + mi * 16 + (lane >> 2);
        #pragma unroll
        for (int ni = 0; ni < 4; ni++) {
            int col_g = n0 + wn * 32 + ni * 8 + (lane & 3) * 2;
            float b0 = bias[col_g], b1 = bias[col_g + 1];
            float2 o0 = make_float2(acc[mi][ni][0] + b0, acc[mi][ni][1] + b1);
            float2 o1 = make_float2(acc[mi][ni][2] + b0, acc[mi][ni][3] + b1);
            *(float2*)(Cout + (size_t)row_g * N + col_g) = o0;
            *(float2*)(Cout + (size_t)(row_g + 8) * N + col_g) = o1;
        }
    }
}

// ---------------------------------------------------------------------------
// Sparsemax over K head-dim + fused split of K AND V into bf16 [hi|lo] rows.
// ---------------------------------------------------------------------------
__global__ __launch_bounds__(256) void sparsemax_kv(
    const float* __restrict__ qkv,
    __nv_bfloat16* __restrict__ Ko, __nv_bfloat16* __restrict__ Vo)
{
    const int lane = threadIdx.x & 31;
    const int wrp  = threadIdx.x >> 5;
    const size_t row = (size_t)blockIdx.x * 8 + wrp;
    const size_t bt  = row >> 4;
    const int    h   = (int)(row & 15);
    const int    b   = (int)(bt >> 11);
    const int    t   = (int)(bt & 2047);

    const float* pk = qkv + bt * C3_ + C_ + h * D_;
    float2 z = *(const float2*)(pk + 2 * lane);
    float v0 = z.x, v1 = z.y;

    #pragma unroll
    for (int k = 2; k <= 64; k <<= 1) {
        #pragma unroll
        for (int j = k >> 1; j > 0; j >>= 1) {
            if (j < 32) {
                float p0 = __shfl_xor_sync(0xffffffffu, v0, j);
                float p1 = __shfl_xor_sync(0xffffffffu, v1, j);
                bool lower = (lane & j) == 0;
                bool up0 = (lane & k) != 0;
                bool up1 = ((lane + 32) & k) != 0;
                v0 = (lower == up0) ? fminf(v0, p0) : fmaxf(v0, p0);
                v1 = (lower == up1) ? fminf(v1, p1) : fmaxf(v1, p1);
            } else {
                float a = fmaxf(v0, v1), bmin = fminf(v0, v1);
                v0 = a; v1 = bmin;
            }
        }
    }

    float c0 = v0;
    #pragma unroll
    for (int o = 1; o < 32; o <<= 1) {
        float tt = __shfl_up_sync(0xffffffffu, c0, o);
        if (lane >= o) c0 += tt;
    }
    float c1 = v1;
    #pragma unroll
    for (int o = 1; o < 32; o <<= 1) {
        float tt = __shfl_up_sync(0xffffffffu, c1, o);
        if (lane >= o) c1 += tt;
    }
    c1 += __shfl_sync(0xffffffffu, c0, 31);

    bool s0 = 1.f + (float)(lane + 1)  * v0 > c0;
    bool s1 = 1.f + (float)(lane + 33) * v1 > c1;
    int rho = __popc(__ballot_sync(0xffffffffu, s0)) +
              __popc(__ballot_sync(0xffffffffu, s1));
    int ridx = rho - 1;
    float csA = __shfl_sync(0xffffffffu, c0, ridx & 31);
    float csB = __shfl_sync(0xffffffffu, c1, ridx & 31);
    float cs  = (ridx < 32) ? csA : csB;
    float tau = (cs - 1.f) / (float)rho;

    float k0 = fmaxf(z.x - tau, 0.f), k1 = fmaxf(z.y - tau, 0.f);
    uint32_t klo; uint32_t khi = split2(k0, k1, klo);
    __nv_bfloat16* kr = Ko + ((size_t)(b * H_ + h) * T_ + t) * 128;
    *(uint32_t*)(kr + 2 * lane)      = khi;
    *(uint32_t*)(kr + 64 + 2 * lane) = klo;

    float2 vv = *(const float2*)(pk + C_ + 2 * lane);
    uint32_t vlo; uint32_t vhi = split2(vv.x, vv.y, vlo);
    __nv_bfloat16* vr = Vo + ((size_t)(b * H_ + h) * T_ + t) * 128;
    *(uint32_t*)(vr + 2 * lane)      = vhi;
    *(uint32_t*)(vr + 64 + 2 * lane) = vlo;
}

// ---------------------------------------------------------------------------
// Flash attention: LPT ordering, cp.async K/V, deduped ldsm (each K/V
// fragment loaded once, both split terms issued from it), JIT P-split,
// 2 CTAs/SM. Fused XSA + split-A3 epilogue.
// ---------------------------------------------------------------------------
#define FROW 136
#define FBUF (128 * FROW)

__global__ __launch_bounds__(256, 2) void flash_hmma(
    const float* __restrict__ qkv,
    const __nv_bfloat16* __restrict__ Ks, const __nv_bfloat16* __restrict__ Vs,
    __nv_bfloat16* __restrict__ A3out)
{
    extern __shared__ __align__(16) __nv_bfloat16 smx[];

    const int tid  = threadIdx.x;
    const int lane = tid & 31;
    const int w    = tid >> 5;
    const int qt = (int)gridDim.x - 1 - (int)blockIdx.x;
    const int h = blockIdx.y, b = blockIdx.z;
    const size_t base = (size_t)b * T_ * C3_;

    const __nv_bfloat16* Kb = Ks + (size_t)(b * H_ + h) * T_ * 128;
    const __nv_bfloat16* Vb = Vs + (size_t)(b * H_ + h) * T_ * 128;
    const uint32_t smb0 = smem_u32(smx);

    auto load_tile = [&](int buf, int kt) {
        const __nv_bfloat16* kg = Kb + (size_t)kt * 64 * 128;
        const __nv_bfloat16* vg = Vb + (size_t)kt * 64 * 128;
        uint32_t sb = smb0 + buf * (FBUF * 2);
        #pragma unroll
        for (int it = 0; it < 4; it++) {
            int c = tid + it * 256;
            int j = c >> 4, seg = c & 15;
            cp16(sb + (uint32_t)(j * FROW) * 2 + seg * 16,        kg + j * 128 + seg * 8);
            cp16(sb + (uint32_t)((64 + j) * FROW) * 2 + seg * 16, vg + j * 128 + seg * 8);
        }
        asm volatile("cp.async.commit_group;" ::: "memory");
    };

    load_tile(0, 0);
    {
        __nv_bfloat16* qb = smx + FBUF;
        for (int i = tid; i < 2048; i += 256) {
            int row = i >> 4, d = (i & 15) * 4;
            float4 f4 = *(const float4*)(qkv + base + (size_t)(qt * 128 + row) * C3_ + h * D_ + d);
            f4.x *= 0.125f; f4.y *= 0.125f; f4.z *= 0.125f; f4.w *= 0.125f;
            uint2 lo; uint2 hi = split4(f4, lo);
            *(uint2*)&qb[row * FROW + d]      = hi;
            *(uint2*)&qb[row * FROW + 64 + d] = lo;
        }
    }
    __syncthreads();

    uint32_t qf[8][4];
    #pragma unroll
    for (int kb = 0; kb < 8; kb++) {
        uint32_t addr = smb0 + FBUF * 2 +
                        (uint32_t)((w * 16 + (lane & 15)) * FROW + kb * 16 + (lane >> 4) * 8) * 2;
        ldsm_x4(qf[kb][0], qf[kb][1], qf[kb][2], qf[kb][3], addr);
    }
    __syncthreads();

    float o[8][4];
    #pragma unroll
    for (int nb = 0; nb < 8; nb++)
        #pragma unroll
        for (int e = 0; e < 4; e++) o[nb][e] = 0.f;
    float m0 = -1e30f, m1 = -1e30f, l0 = 0.f, l1 = 0.f;

    const int qrow_g0 = qt * 128 + w * 16 + (lane >> 2);
    const int nkt = (qt + 1) * 2;

    for (int kt = 0; kt < nkt; kt++) {
        if (kt + 1 < nkt) load_tile((kt + 1) & 1, kt + 1);
        else asm volatile("cp.async.commit_group;" ::: "memory");
        asm volatile("cp.async.wait_group 1;" ::: "memory");
        __syncthreads();

        const uint32_t smb = smb0 + (kt & 1) * (FBUF * 2);

        // ---- S = Qh·Kh + Ql·Kh + Qh·Kl (Kh frags loaded ONCE, two mma terms) ----
        float s[8][4];
        #pragma unroll
        for (int nb = 0; nb < 8; nb++)
            #pragma unroll
            for (int e = 0; e < 4; e++) s[nb][e] = 0.f;

        #pragma unroll
        for (int j = 0; j < 4; j++) {           // Kh cols j*16
            #pragma unroll
            for (int nbp = 0; nbp < 4; nbp++) {
                uint32_t r0, r1, r2, r3;
                uint32_t addr = smb +
                    (uint32_t)((nbp * 16 + (lane & 7) + ((lane >> 4) & 1) * 8) * FROW
                               + j * 16 + ((lane >> 3) & 1) * 8) * 2;
                ldsm_x4(r0, r1, r2, r3, addr);
                mma16816(s[nbp * 2],     qf[j],     r0, r1);   // Qh·Kh
                mma16816(s[nbp * 2 + 1], qf[j],     r2, r3);
                mma16816(s[nbp * 2],     qf[j + 4], r0, r1);   // Ql·Kh
                mma16816(s[nbp * 2 + 1], qf[j + 4], r2, r3);
            }
        }
        #pragma unroll
        for (int j = 0; j < 4; j++) {           // Kl cols 64 + j*16
            #pragma unroll
            for (int nbp = 0; nbp < 4; nbp++) {
                uint32_t r0, r1, r2, r3;
                uint32_t addr = smb +
                    (uint32_t)((nbp * 16 + (lane & 7) + ((lane >> 4) & 1) * 8) * FROW
                               + 64 + j * 16 + ((lane >> 3) & 1) * 8) * 2;
                ldsm_x4(r0, r1, r2, r3, addr);
                mma16816(s[nbp * 2],     qf[j], r0, r1);        // Qh·Kl
                mma16816(s[nbp * 2 + 1], qf[j], r2, r3);
            }
        }

        // ---- causal mask ----
        if (kt * 64 + 63 > qt * 128 + w * 16) {
            #pragma unroll
            for (int nb = 0; nb < 8; nb++) {
                int col = kt * 64 + nb * 8 + (lane & 3) * 2;
                if (col     > qrow_g0)     s[nb][0] = -1e30f;
                if (col + 1 > qrow_g0)     s[nb][1] = -1e30f;
                if (col     > qrow_g0 + 8) s[nb][2] = -1e30f;
                if (col + 1 > qrow_g0 + 8) s[nb][3] = -1e30f;
            }
        }

        // ---- online softmax ----
        float tm0 = -1e30f, tm1 = -1e30f;
        #pragma unroll
        for (int nb = 0; nb < 8; nb++) {
            tm0 = fmaxf(tm0, fmaxf(s[nb][0], s[nb][1]));
            tm1 = fmaxf(tm1, fmaxf(s[nb][2], s[nb][3]));
        }
        tm0 = fmaxf(tm0, __shfl_xor_sync(0xffffffffu, tm0, 1));
        tm0 = fmaxf(tm0, __shfl_xor_sync(0xffffffffu, tm0, 2));
        tm1 = fmaxf(tm1, __shfl_xor_sync(0xffffffffu, tm1, 1));
        tm1 = fmaxf(tm1, __shfl_xor_sync(0xffffffffu, tm1, 2));

        float m0n = fmaxf(m0, tm0), m1n = fmaxf(m1, tm1);
        float corr0 = __expf(m0 - m0n), corr1 = __expf(m1 - m1n);
        m0 = m0n; m1 = m1n;
        l0 *= corr0; l1 *= corr1;

        #pragma unroll
        for (int nb = 0; nb < 8; nb++) {
            s[nb][0] = __expf(s[nb][0] - m0);
            s[nb][1] = __expf(s[nb][1] - m0);
            s[nb][2] = __expf(s[nb][2] - m1);
            s[nb][3] = __expf(s[nb][3] - m1);
            l0 += s[nb][0] + s[nb][1];
            l1 += s[nb][2] + s[nb][3];
            o[nb][0] *= corr0; o[nb][1] *= corr0;
            o[nb][2] *= corr1; o[nb][3] *= corr1;
        }

        // ---- O += Ph·Vh + Pl·Vh + Ph·Vl, JIT split per 16-row quarter,
        //      Vh frags loaded ONCE for both Ph and Pl terms ----
        #pragma unroll
        for (int j = 0; j < 4; j++) {
            uint32_t ph[4], pl[4];
            #pragma unroll
            for (int q = 0; q < 4; q++) {
                int nb = j * 2 + (q >> 1);
                uint32_t plq;
                ph[q] = split2(s[nb][(q & 1) * 2], s[nb][(q & 1) * 2 + 1], plq);
                pl[q] = plq;
            }
            int krow = 64 + j * 16;
            #pragma unroll
            for (int nbp = 0; nbp < 4; nbp++) {     // Vh: both Ph and Pl terms
                uint32_t r0, r1, r2, r3;
                uint32_t addr = smb +
                    (uint32_t)((krow + (lane & 15)) * FROW + nbp * 16 + (lane >> 4) * 8) * 2;
                ldsm_x4t(r0, r1, r2, r3, addr);
                mma16816(o[nbp * 2],     ph, r0, r1);
                mma16816(o[nbp * 2 + 1], ph, r2, r3);
                mma16816(o[nbp * 2],     pl, r0, r1);
                mma16816(o[nbp * 2 + 1], pl, r2, r3);
            }
            #pragma unroll
            for (int nbp = 0; nbp < 4; nbp++) {     // Vl: Ph term only
                uint32_t r0, r1, r2, r3;
                uint32_t addr = smb +
                    (uint32_t)((krow + (lane & 15)) * FROW + 64 + nbp * 16 + (lane >> 4) * 8) * 2;
                ldsm_x4t(r0, r1, r2, r3, addr);
                mma16816(o[nbp * 2],     ph, r0, r1);
                mma16816(o[nbp * 2 + 1], ph, r2, r3);
            }
        }
        __syncthreads();
    }

    // ---- finalize: normalize + XSA, write split-A3 directly ----
    l0 += __shfl_xor_sync(0xffffffffu, l0, 1);
    l0 += __shfl_xor_sync(0xffffffffu, l0, 2);
    l1 += __shfl_xor_sync(0xffffffffu, l1, 1);
    l1 += __shfl_xor_sync(0xffffffffu, l1, 2);
    float inv0 = 1.f / l0, inv1 = 1.f / l1;

    float2 vr0[8], vr1[8];
    float sov0 = 0.f, svv0 = 0.f, sov1 = 0.f, svv1 = 0.f;
    const float* vb = qkv + base + 2 * C_ + h * D_;
    #pragma unroll
    for (int nb = 0; nb < 8; nb++) {
        int d = nb * 8 + (lane & 3) * 2;
        vr0[nb] = *(const float2*)(vb + (size_t)qrow_g0 * C3_ + d);
        vr1[nb] = *(const float2*)(vb + (size_t)(qrow_g0 + 8) * C3_ + d);
        o[nb][0] *= inv0; o[nb][1] *= inv0; o[nb][2] *= inv1; o[nb][3] *= inv1;
        sov0 += o[nb][0] * vr0[nb].x + o[nb][1] * vr0[nb].y;
        svv0 += vr0[nb].x * vr0[nb].x + vr0[nb].y * vr0[nb].y;
        sov1 += o[nb][2] * vr1[nb].x + o[nb][3] * vr1[nb].y;
        svv1 += vr1[nb].x * vr1[nb].x + vr1[nb].y * vr1[nb].y;
    }
    sov0 += __shfl_xor_sync(0xffffffffu, sov0, 1);
    sov0 += __shfl_xor_sync(0xffffffffu, sov0, 2);
    svv0 += __shfl_xor_sync(0xffffffffu, svv0, 1);
    svv0 += __shfl_xor_sync(0xffffffffu, svv0, 2);
    sov1 += __shfl_xor_sync(0xffffffffu, sov1, 1);
    sov1 += __shfl_xor_sync(0xffffffffu, sov1, 2);
    svv1 += __shfl_xor_sync(0xffffffffu, svv1, 1);
    svv1 += __shfl_xor_sync(0xffffffffu, svv1, 2);

    float mx0 = fmaxf(sqrtf(svv0), 1e-12f);
    float mx1 = fmaxf(sqrtf(svv1), 1e-12f);
    float c0 = sov0 / (mx0 * mx0), c1 = sov1 / (mx1 * mx1);

    __nv_bfloat16* a0 = A3out + (size_t)(b * T_ + qrow_g0) * K3_;
    __nv_bfloat16* a1 = a0 + 8 * K3_;
    #pragma unroll
    for (int nb = 0; nb < 8; nb++) {
        int k = h * D_ + nb * 8 + (lane & 3) * 2;
        float y00 = o[nb][0] - c0 * vr0[nb].x, y01 = o[nb][1] - c0 * vr0[nb].y;
        float y10 = o[nb][2] - c1 * vr1[nb].x, y11 = o[nb][3] - c1 * vr1[nb].y;
        uint32_t lo0; uint32_t hi0 = split2(y00, y01, lo0);
        uint32_t lo1; uint32_t hi1 = split2(y10, y11, lo1);
        *(uint32_t*)(a0 + k)        = hi0;
        *(uint32_t*)(a0 + 1024 + k) = lo0;
        *(uint32_t*)(a0 + 2048 + k) = hi0;
        *(uint32_t*)(a1 + k)        = hi1;
        *(uint32_t*)(a1 + 1024 + k) = lo1;
        *(uint32_t*)(a1 + 2048 + k) = hi1;
    }
}

// ---------------------------------------------------------------------------
extern "C" void kernel_launch(void* const* d_in, const int* in_sizes, int n_in,
                              void* d_out, int out_size)
{
    const float* x  = (const float*)d_in[0];
    const float* Wa = (const float*)d_in[1];
    const float* ba = (const float*)d_in[2];
    const float* Wp = (const float*)d_in[3];
    const float* bp = (const float*)d_in[4];
    float* out = (float*)d_out;

    float* qkv;
    __nv_bfloat16 *A3, *B3, *Kp, *Vp;
    cudaGetSymbolAddress((void**)&qkv, g_qkv);
    cudaGetSymbolAddress((void**)&A3,  g_A3);
    cudaGetSymbolAddress((void**)&B3,  g_B3);
    cudaGetSymbolAddress((void**)&Kp,  g_K);
    cudaGetSymbolAddress((void**)&Vp,  g_V);

    const int M = B_ * T_;
    const int flash_smem = 2 * FBUF * 2;            // 69.6 KB
    const int gemm_smem  = NSTG * 2 * OPBYTES;      // 110.6 KB

    static int attr_set = 0;
    if (!attr_set) {
        cudaFuncSetAttribute(flash_hmma, cudaFuncAttributeMaxDynamicSharedMemorySize, flash_smem);
        cudaFuncSetAttribute(hmma_gemm,  cudaFuncAttributeMaxDynamicSharedMemorySize, gemm_smem);
        attr_set = 1;
    }

    prep_W<<<dim3(C3_ / 32, C_ / 32), 256>>>(Wa, B3, C3_);
    split_A<<<(M * C_) / (256 * 8), 256>>>(x, A3);
    hmma_gemm<<<dim3(C3_ / 128, M / 128), 256, gemm_smem>>>(A3, B3, ba, qkv, M, C3_, K3_);

    sparsemax_kv<<<(M * H_) / 8, 256>>>(qkv, Kp, Vp);

    flash_hmma<<<dim3(T_ / 128, H_, B_), 256, flash_smem>>>(qkv, Kp, Vp, A3);

    prep_W<<<dim3(C_ / 32, C_ / 32), 256>>>(Wp, B3, C_);
    hmma_gemm<<<dim3(C_ / 128, M / 128), 256, gemm_smem>>>(A3, B3, bp, out, M, C_, K3_);
}

// round 14
// speedup vs baseline: 1.6969x; 1.0054x over previous
#include <cuda_runtime.h>
#include <cuda_bf16.h>
#include <math.h>
#include <stdint.h>

#define B_  4
#define T_  2048
#define C_  1024
#define H_  16
#define D_  64
#define C3_ 3072
#define K3_ 3072

typedef unsigned long long u64;

__device__ float g_qkv[(size_t)B_ * T_ * C3_];
__device__ __nv_bfloat16 g_A3[(size_t)B_ * T_ * K3_];
__device__ __nv_bfloat16 g_B3[(size_t)C3_ * K3_];
__device__ __nv_bfloat16 g_Q[(size_t)B_ * H_ * T_ * 128];   // [b,h,t][hi64|lo64], pre-scaled
__device__ __nv_bfloat16 g_K[(size_t)B_ * H_ * T_ * 128];
__device__ __nv_bfloat16 g_V[(size_t)B_ * H_ * T_ * 128];

// ---- helpers ----
__device__ __forceinline__ uint32_t smem_u32(const void* p) {
    uint32_t a;
    asm("{ .reg .u64 t; cvta.to.shared.u64 t, %1; cvt.u32.u64 %0, t; }" : "=r"(a) : "l"(p));
    return a;
}
__device__ __forceinline__ void cp16(uint32_t dst, const void* src) {
    asm volatile("cp.async.cg.shared.global [%0], [%1], 16;" :: "r"(dst), "l"(src));
}
__device__ __forceinline__ void ldsm_x4(uint32_t& r0, uint32_t& r1, uint32_t& r2, uint32_t& r3,
                                        uint32_t addr) {
    asm volatile("ldmatrix.sync.aligned.m8n8.x4.shared.b16 {%0,%1,%2,%3},[%4];"
                 : "=r"(r0), "=r"(r1), "=r"(r2), "=r"(r3) : "r"(addr));
}
__device__ __forceinline__ void ldsm_x4t(uint32_t& r0, uint32_t& r1, uint32_t& r2, uint32_t& r3,
                                         uint32_t addr) {
    asm volatile("ldmatrix.sync.aligned.m8n8.x4.trans.shared.b16 {%0,%1,%2,%3},[%4];"
                 : "=r"(r0), "=r"(r1), "=r"(r2), "=r"(r3) : "r"(addr));
}
__device__ __forceinline__ void mma16816(float* c, const uint32_t* a, uint32_t b0, uint32_t b1) {
    asm volatile(
        "mma.sync.aligned.m16n8k16.row.col.f32.bf16.bf16.f32 "
        "{%0,%1,%2,%3},{%4,%5,%6,%7},{%8,%9},{%0,%1,%2,%3};"
        : "+f"(c[0]), "+f"(c[1]), "+f"(c[2]), "+f"(c[3])
        : "r"(a[0]), "r"(a[1]), "r"(a[2]), "r"(a[3]), "r"(b0), "r"(b1));
}
__device__ __forceinline__ uint32_t pkbf(float lo, float hi) {
    uint32_t r; asm("cvt.rn.bf16x2.f32 %0,%1,%2;" : "=r"(r) : "f"(hi), "f"(lo)); return r;
}
__device__ __forceinline__ uint32_t split2(float a, float b, uint32_t& lo) {
    uint32_t hp = pkbf(a, b);
    float la = a - __uint_as_float(hp << 16);
    float lb = b - __uint_as_float(hp & 0xFFFF0000u);
    lo = pkbf(la, lb);
    return hp;
}
__device__ __forceinline__ uint2 split4(float4 f, uint2& lo) {
    uint32_t l0, l1;
    uint32_t h0 = split2(f.x, f.y, l0);
    uint32_t h1 = split2(f.z, f.w, l1);
    lo = make_uint2(l0, l1);
    return make_uint2(h0, h1);
}
// reconstruct 2 fp32 from packed (hi,lo) bf16x2 words
__device__ __forceinline__ float2 rec2(uint32_t hw, uint32_t lw) {
    float2 r;
    r.x = __uint_as_float(hw << 16)          + __uint_as_float(lw << 16);
    r.y = __uint_as_float(hw & 0xFFFF0000u)  + __uint_as_float(lw & 0xFFFF0000u);
    return r;
}

// ---------------------------------------------------------------------------
// split_A: src fp32 [M,1024] -> dst bf16 [M,3072] = [hi|lo|hi]
// ---------------------------------------------------------------------------
__global__ __launch_bounds__(256) void split_A(
    const float* __restrict__ src, __nv_bfloat16* __restrict__ dst)
{
    size_t idx = ((size_t)blockIdx.x * 256 + threadIdx.x) * 8;
    int m = (int)(idx >> 10), k = (int)(idx & 1023);
    float4 f0 = *(const float4*)(src + idx);
    float4 f1 = *(const float4*)(src + idx + 4);
    uint2 l0, l1;
    uint2 h0 = split4(f0, l0);
    uint2 h1 = split4(f1, l1);
    __nv_bfloat16* r = dst + (size_t)m * K3_;
    *(uint4*)(r + k)        = make_uint4(h0.x, h0.y, h1.x, h1.y);
    *(uint4*)(r + 1024 + k) = make_uint4(l0.x, l0.y, l1.x, l1.y);
    *(uint4*)(r + 2048 + k) = make_uint4(h0.x, h0.y, h1.x, h1.y);
}

// ---------------------------------------------------------------------------
// prep_W: W fp32 [1024, N] -> Bo bf16 [N,3072] = [hi|hi|lo]
// ---------------------------------------------------------------------------
__global__ __launch_bounds__(256) void prep_W(
    const float* __restrict__ W, __nv_bfloat16* __restrict__ Bo, int N)
{
    __shared__ float t[32][33];
    int n0 = blockIdx.x * 32, k0 = blockIdx.y * 32;
    {
        int tx = threadIdx.x & 31, ty = threadIdx.x >> 5;
        #pragma unroll
        for (int i = 0; i < 4; i++)
            t[ty + i * 8][tx] = W[(size_t)(k0 + ty + i * 8) * N + n0 + tx];
    }
    __syncthreads();
    int kk = (threadIdx.x & 15) * 2, ny = threadIdx.x >> 4;
    #pragma unroll
    for (int i = 0; i < 2; i++) {
        int n = ny + i * 16;
        uint32_t lp;
        uint32_t hp = split2(t[kk][n], t[kk + 1][n], lp);
        size_t r = (size_t)(n0 + n) * K3_;
        *(uint32_t*)(Bo + r + k0 + kk)        = hp;
        *(uint32_t*)(Bo + r + 1024 + k0 + kk) = hp;
        *(uint32_t*)(Bo + r + 2048 + k0 + kk) = lp;
    }
}

// ---------------------------------------------------------------------------
// HMMA GEMM: r8 config (128x128 tile, BK=64, 3-stage).
// ---------------------------------------------------------------------------
#define BK    64
#define ROWE  72
#define NSTG  3
#define OPBYTES (128 * ROWE * 2)

__global__ __launch_bounds__(256) void hmma_gemm(
    const __nv_bfloat16* __restrict__ A, const __nv_bfloat16* __restrict__ Bk,
    const float* __restrict__ bias, float* __restrict__ Cout,
    int M, int N, int K)
{
    extern __shared__ __align__(16) __nv_bfloat16 gsm[];

    const int tid  = threadIdx.x;
    const int lane = tid & 31;
    const int wid  = tid >> 5;
    const int wm   = wid >> 2;
    const int wn   = wid & 3;
    const int m0 = blockIdx.y * 128, n0 = blockIdx.x * 128;

    const uint32_t smb = smem_u32(gsm);

    auto load_tile = [&](int stg, int kt) {
        const __nv_bfloat16* Ag = A + (size_t)m0 * K + kt * BK;
        const __nv_bfloat16* Bg = Bk + (size_t)n0 * K + kt * BK;
        uint32_t sA = smb + stg * (2 * OPBYTES);
        uint32_t sB = sA + OPBYTES;
        #pragma unroll
        for (int it = 0; it < 4; it++) {
            int c = tid + it * 256;
            int row = c >> 3, seg = c & 7;
            uint32_t doff = (uint32_t)(row * ROWE + seg * 8) * 2;
            cp16(sA + doff, Ag + (size_t)row * K + seg * 8);
            cp16(sB + doff, Bg + (size_t)row * K + seg * 8);
        }
        asm volatile("cp.async.commit_group;" ::: "memory");
    };

    float acc[4][4][4];
    #pragma unroll
    for (int i = 0; i < 4; i++)
        #pragma unroll
        for (int j = 0; j < 4; j++)
            #pragma unroll
            for (int e = 0; e < 4; e++) acc[i][j][e] = 0.f;

    const int nkt = K / BK;
    load_tile(0, 0);
    load_tile(1, 1);

    const int a_row = wm * 64 + (lane & 15);
    const int a_ko  = (lane >> 4) * 8;
    const int b_row = wn * 32 + (lane & 7) + ((lane >> 4) & 1) * 8;
    const int b_ko  = ((lane >> 3) & 1) * 8;

    int stg = 0;
    for (int kt = 0; kt < nkt; kt++) {
        if (kt + 2 < nkt) {
            int s2 = stg + 2; if (s2 >= NSTG) s2 -= NSTG;
            load_tile(s2, kt + 2);
        } else {
            asm volatile("cp.async.commit_group;" ::: "memory");
        }
        asm volatile("cp.async.wait_group 2;" ::: "memory");
        __syncthreads();

        const uint32_t aT = smb + stg * (2 * OPBYTES);
        const uint32_t bT = aT + OPBYTES;

        #pragma unroll
        for (int ks = 0; ks < 4; ks++) {
            uint32_t af[4][4];
            #pragma unroll
            for (int mi = 0; mi < 4; mi++)
                ldsm_x4(af[mi][0], af[mi][1], af[mi][2], af[mi][3],
                        aT + (uint32_t)((a_row + mi * 16) * ROWE + ks * 16 + a_ko) * 2);
            uint32_t bf[4][2];
            #pragma unroll
            for (int nb = 0; nb < 2; nb++) {
                uint32_t r0, r1, r2, r3;
                ldsm_x4(r0, r1, r2, r3,
                        bT + (uint32_t)((b_row + nb * 16) * ROWE + ks * 16 + b_ko) * 2);
                bf[nb * 2][0] = r0; bf[nb * 2][1] = r1;
                bf[nb * 2 + 1][0] = r2; bf[nb * 2 + 1][1] = r3;
            }
            #pragma unroll
            for (int mi = 0; mi < 4; mi++)
                #pragma unroll
                for (int ni = 0; ni < 4; ni++)
                    mma16816(acc[mi][ni], af[mi], bf[ni][0], bf[ni][1]);
        }
        __syncthreads();
        if (++stg >= NSTG) stg = 0;
    }

    #pragma unroll
    for (int mi = 0; mi < 4; mi++) {
        int row_g = m0 + wm * 64 + mi * 16 + (lane >> 2);
        #pragma unroll
        for (int ni = 0; ni < 4; ni++) {
            int col_g = n0 + wn * 32 + ni * 8 + (lane & 3) * 2;
            float b0 = bias[col_g], b1 = bias[col_g + 1];
            float2 o0 = make_float2(acc[mi][ni][0] + b0, acc[mi][ni][1] + b1);
            float2 o1 = make_float2(acc[mi][ni][2] + b0, acc[mi][ni][3] + b1);
            *(float2*)(Cout + (size_t)row_g * N + col_g) = o0;
            *(float2*)(Cout + (size_t)(row_g + 8) * N + col_g) = o1;
        }
    }
}

// ---------------------------------------------------------------------------
// prep_qkv: warp per (b,t,h) row.
//   Q: scale 1/8 + split -> g_Q ; K: sparsemax + split -> g_K ; V: split -> g_V
// ---------------------------------------------------------------------------
__global__ __launch_bounds__(256) void prep_qkv(
    const float* __restrict__ qkv,
    __nv_bfloat16* __restrict__ Qo, __nv_bfloat16* __restrict__ Ko,
    __nv_bfloat16* __restrict__ Vo)
{
    const int lane = threadIdx.x & 31;
    const int wrp  = threadIdx.x >> 5;
    const size_t row = (size_t)blockIdx.x * 8 + wrp;
    const size_t bt  = row >> 4;
    const int    h   = (int)(row & 15);
    const int    b   = (int)(bt >> 11);
    const int    t   = (int)(bt & 2047);
    const size_t orow = ((size_t)(b * H_ + h) * T_ + t) * 128;

    // --- Q: scale + split ---
    {
        const float* pq = qkv + bt * C3_ + h * D_;
        float2 q = *(const float2*)(pq + 2 * lane);
        uint32_t qlo; uint32_t qhi = split2(q.x * 0.125f, q.y * 0.125f, qlo);
        __nv_bfloat16* qr = Qo + orow;
        *(uint32_t*)(qr + 2 * lane)      = qhi;
        *(uint32_t*)(qr + 64 + 2 * lane) = qlo;
    }

    // --- K: sparsemax + split ---
    const float* pk = qkv + bt * C3_ + C_ + h * D_;
    float2 z = *(const float2*)(pk + 2 * lane);
    float v0 = z.x, v1 = z.y;

    #pragma unroll
    for (int k = 2; k <= 64; k <<= 1) {
        #pragma unroll
        for (int j = k >> 1; j > 0; j >>= 1) {
            if (j < 32) {
                float p0 = __shfl_xor_sync(0xffffffffu, v0, j);
                float p1 = __shfl_xor_sync(0xffffffffu, v1, j);
                bool lower = (lane & j) == 0;
                bool up0 = (lane & k) != 0;
                bool up1 = ((lane + 32) & k) != 0;
                v0 = (lower == up0) ? fminf(v0, p0) : fmaxf(v0, p0);
                v1 = (lower == up1) ? fminf(v1, p1) : fmaxf(v1, p1);
            } else {
                float a = fmaxf(v0, v1), bmin = fminf(v0, v1);
                v0 = a; v1 = bmin;
            }
        }
    }

    float c0 = v0;
    #pragma unroll
    for (int o = 1; o < 32; o <<= 1) {
        float tt = __shfl_up_sync(0xffffffffu, c0, o);
        if (lane >= o) c0 += tt;
    }
    float c1 = v1;
    #pragma unroll
    for (int o = 1; o < 32; o <<= 1) {
        float tt = __shfl_up_sync(0xffffffffu, c1, o);
        if (lane >= o) c1 += tt;
    }
    c1 += __shfl_sync(0xffffffffu, c0, 31);

    bool s0 = 1.f + (float)(lane + 1)  * v0 > c0;
    bool s1 = 1.f + (float)(lane + 33) * v1 > c1;
    int rho = __popc(__ballot_sync(0xffffffffu, s0)) +
              __popc(__ballot_sync(0xffffffffu, s1));
    int ridx = rho - 1;
    float csA = __shfl_sync(0xffffffffu, c0, ridx & 31);
    float csB = __shfl_sync(0xffffffffu, c1, ridx & 31);
    float cs  = (ridx < 32) ? csA : csB;
    float tau = (cs - 1.f) / (float)rho;

    float k0 = fmaxf(z.x - tau, 0.f), k1 = fmaxf(z.y - tau, 0.f);
    uint32_t klo; uint32_t khi = split2(k0, k1, klo);
    __nv_bfloat16* kr = Ko + orow;
    *(uint32_t*)(kr + 2 * lane)      = khi;
    *(uint32_t*)(kr + 64 + 2 * lane) = klo;

    // --- V: split ---
    float2 vv = *(const float2*)(pk + C_ + 2 * lane);
    uint32_t vlo; uint32_t vhi = split2(vv.x, vv.y, vlo);
    __nv_bfloat16* vr = Vo + orow;
    *(uint32_t*)(vr + 2 * lane)      = vhi;
    *(uint32_t*)(vr + 64 + 2 * lane) = vlo;
}

// ---------------------------------------------------------------------------
// Flash attention: pure cp.async consumer (Q, K, V all pre-split bf16),
// LPT ordering, deduped ldsm, JIT P-split, 2 CTAs/SM, XSA from bf16 V,
// split-A3 epilogue.
// ---------------------------------------------------------------------------
#define FROW 136
#define FBUF (128 * FROW)

__global__ __launch_bounds__(256, 2) void flash_hmma(
    const __nv_bfloat16* __restrict__ Qs,
    const __nv_bfloat16* __restrict__ Ks, const __nv_bfloat16* __restrict__ Vs,
    __nv_bfloat16* __restrict__ A3out)
{
    extern __shared__ __align__(16) __nv_bfloat16 smx[];

    const int tid  = threadIdx.x;
    const int lane = tid & 31;
    const int w    = tid >> 5;
    const int qt = (int)gridDim.x - 1 - (int)blockIdx.x;
    const int h = blockIdx.y, b = blockIdx.z;

    const size_t plane = (size_t)(b * H_ + h) * T_;
    const __nv_bfloat16* Kb = Ks + plane * 128;
    const __nv_bfloat16* Vb = Vs + plane * 128;
    const uint32_t smb0 = smem_u32(smx);

    auto load_tile = [&](int buf, int kt) {
        const __nv_bfloat16* kg = Kb + (size_t)kt * 64 * 128;
        const __nv_bfloat16* vg = Vb + (size_t)kt * 64 * 128;
        uint32_t sb = smb0 + buf * (FBUF * 2);
        #pragma unroll
        for (int it = 0; it < 4; it++) {
            int c = tid + it * 256;
            int j = c >> 4, seg = c & 15;
            cp16(sb + (uint32_t)(j * FROW) * 2 + seg * 16,        kg + j * 128 + seg * 8);
            cp16(sb + (uint32_t)((64 + j) * FROW) * 2 + seg * 16, vg + j * 128 + seg * 8);
        }
        asm volatile("cp.async.commit_group;" ::: "memory");
    };

    // tile0 K/V + Q tile (128 rows x 256B = 2048 x 16B chunks) via cp.async
    load_tile(0, 0);
    {
        const __nv_bfloat16* qg = Qs + (plane + (size_t)qt * 128) * 128;
        uint32_t qb = smb0 + FBUF * 2;   // staged in buffer 1 (consumed before tile1)
        #pragma unroll
        for (int it = 0; it < 8; it++) {
            int c = tid + it * 256;
            int row = c >> 4, seg = c & 15;
            cp16(qb + (uint32_t)(row * FROW) * 2 + seg * 16, qg + row * 128 + seg * 8);
        }
        asm volatile("cp.async.commit_group;" ::: "memory");
    }
    asm volatile("cp.async.wait_group 0;" ::: "memory");
    __syncthreads();

    uint32_t qf[8][4];
    #pragma unroll
    for (int kb = 0; kb < 8; kb++) {
        uint32_t addr = smb0 + FBUF * 2 +
                        (uint32_t)((w * 16 + (lane & 15)) * FROW + kb * 16 + (lane >> 4) * 8) * 2;
        ldsm_x4(qf[kb][0], qf[kb][1], qf[kb][2], qf[kb][3], addr);
    }
    __syncthreads();

    float o[8][4];
    #pragma unroll
    for (int nb = 0; nb < 8; nb++)
        #pragma unroll
        for (int e = 0; e < 4; e++) o[nb][e] = 0.f;
    float m0 = -1e30f, m1 = -1e30f, l0 = 0.f, l1 = 0.f;

    const int qrow_g0 = qt * 128 + w * 16 + (lane >> 2);
    const int nkt = (qt + 1) * 2;

    for (int kt = 0; kt < nkt; kt++) {
        if (kt + 1 < nkt) load_tile((kt + 1) & 1, kt + 1);
        else asm volatile("cp.async.commit_group;" ::: "memory");
        asm volatile("cp.async.wait_group 1;" ::: "memory");
        __syncthreads();

        const uint32_t smb = smb0 + (kt & 1) * (FBUF * 2);

        // ---- S = Qh·Kh + Ql·Kh + Qh·Kl (Kh frags loaded once) ----
        float s[8][4];
        #pragma unroll
        for (int nb = 0; nb < 8; nb++)
            #pragma unroll
            for (int e = 0; e < 4; e++) s[nb][e] = 0.f;

        #pragma unroll
        for (int j = 0; j < 4; j++) {
            #pragma unroll
            for (int nbp = 0; nbp < 4; nbp++) {
                uint32_t r0, r1, r2, r3;
                uint32_t addr = smb +
                    (uint32_t)((nbp * 16 + (lane & 7) + ((lane >> 4) & 1) * 8) * FROW
                               + j * 16 + ((lane >> 3) & 1) * 8) * 2;
                ldsm_x4(r0, r1, r2, r3, addr);
                mma16816(s[nbp * 2],     qf[j],     r0, r1);
                mma16816(s[nbp * 2 + 1], qf[j],     r2, r3);
                mma16816(s[nbp * 2],     qf[j + 4], r0, r1);
                mma16816(s[nbp * 2 + 1], qf[j + 4], r2, r3);
            }
        }
        #pragma unroll
        for (int j = 0; j < 4; j++) {
            #pragma unroll
            for (int nbp = 0; nbp < 4; nbp++) {
                uint32_t r0, r1, r2, r3;
                uint32_t addr = smb +
                    (uint32_t)((nbp * 16 + (lane & 7) + ((lane >> 4) & 1) * 8) * FROW
                               + 64 + j * 16 + ((lane >> 3) & 1) * 8) * 2;
                ldsm_x4(r0, r1, r2, r3, addr);
                mma16816(s[nbp * 2],     qf[j], r0, r1);
                mma16816(s[nbp * 2 + 1], qf[j], r2, r3);
            }
        }

        // ---- causal mask ----
        if (kt * 64 + 63 > qt * 128 + w * 16) {
            #pragma unroll
            for (int nb = 0; nb < 8; nb++) {
                int col = kt * 64 + nb * 8 + (lane & 3) * 2;
                if (col     > qrow_g0)     s[nb][0] = -1e30f;
                if (col + 1 > qrow_g0)     s[nb][1] = -1e30f;
                if (col     > qrow_g0 + 8) s[nb][2] = -1e30f;
                if (col + 1 > qrow_g0 + 8) s[nb][3] = -1e30f;
            }
        }

        // ---- online softmax ----
        float tm0 = -1e30f, tm1 = -1e30f;
        #pragma unroll
        for (int nb = 0; nb < 8; nb++) {
            tm0 = fmaxf(tm0, fmaxf(s[nb][0], s[nb][1]));
            tm1 = fmaxf(tm1, fmaxf(s[nb][2], s[nb][3]));
        }
        tm0 = fmaxf(tm0, __shfl_xor_sync(0xffffffffu, tm0, 1));
        tm0 = fmaxf(tm0, __shfl_xor_sync(0xffffffffu, tm0, 2));
        tm1 = fmaxf(tm1, __shfl_xor_sync(0xffffffffu, tm1, 1));
        tm1 = fmaxf(tm1, __shfl_xor_sync(0xffffffffu, tm1, 2));

        float m0n = fmaxf(m0, tm0), m1n = fmaxf(m1, tm1);
        float corr0 = __expf(m0 - m0n), corr1 = __expf(m1 - m1n);
        m0 = m0n; m1 = m1n;
        l0 *= corr0; l1 *= corr1;

        #pragma unroll
        for (int nb = 0; nb < 8; nb++) {
            s[nb][0] = __expf(s[nb][0] - m0);
            s[nb][1] = __expf(s[nb][1] - m0);
            s[nb][2] = __expf(s[nb][2] - m1);
            s[nb][3] = __expf(s[nb][3] - m1);
            l0 += s[nb][0] + s[nb][1];
            l1 += s[nb][2] + s[nb][3];
            o[nb][0] *= corr0; o[nb][1] *= corr0;
            o[nb][2] *= corr1; o[nb][3] *= corr1;
        }

        // ---- O += Ph·Vh + Pl·Vh + Ph·Vl (JIT split, Vh frags loaded once) ----
        #pragma unroll
        for (int j = 0; j < 4; j++) {
            uint32_t ph[4], pl[4];
            #pragma unroll
            for (int q = 0; q < 4; q++) {
                int nb = j * 2 + (q >> 1);
                uint32_t plq;
                ph[q] = split2(s[nb][(q & 1) * 2], s[nb][(q & 1) * 2 + 1], plq);
                pl[q] = plq;
            }
            int krow = 64 + j * 16;
            #pragma unroll
            for (int nbp = 0; nbp < 4; nbp++) {
                uint32_t r0, r1, r2, r3;
                uint32_t addr = smb +
                    (uint32_t)((krow + (lane & 15)) * FROW + nbp * 16 + (lane >> 4) * 8) * 2;
                ldsm_x4t(r0, r1, r2, r3, addr);
                mma16816(o[nbp * 2],     ph, r0, r1);
                mma16816(o[nbp * 2 + 1], ph, r2, r3);
                mma16816(o[nbp * 2],     pl, r0, r1);
                mma16816(o[nbp * 2 + 1], pl, r2, r3);
            }
            #pragma unroll
            for (int nbp = 0; nbp < 4; nbp++) {
                uint32_t r0, r1, r2, r3;
                uint32_t addr = smb +
                    (uint32_t)((krow + (lane & 15)) * FROW + 64 + nbp * 16 + (lane >> 4) * 8) * 2;
                ldsm_x4t(r0, r1, r2, r3, addr);
                mma16816(o[nbp * 2],     ph, r0, r1);
                mma16816(o[nbp * 2 + 1], ph, r2, r3);
            }
        }
        __syncthreads();
    }

    // ---- finalize: normalize + XSA (V reconstructed from bf16 hi+lo) ----
    l0 += __shfl_xor_sync(0xffffffffu, l0, 1);
    l0 += __shfl_xor_sync(0xffffffffu, l0, 2);
    l1 += __shfl_xor_sync(0xffffffffu, l1, 1);
    l1 += __shfl_xor_sync(0xffffffffu, l1, 2);
    float inv0 = 1.f / l0, inv1 = 1.f / l1;

    const __nv_bfloat16* vrow0 = Vb + (size_t)qrow_g0 * 128;
    const __nv_bfloat16* vrow1 = vrow0 + 8 * 128;

    float2 vr0[8], vr1[8];
    float sov0 = 0.f, svv0 = 0.f, sov1 = 0.f, svv1 = 0.f;
    #pragma unroll
    for (int nb = 0; nb < 8; nb++) {
        int d = nb * 8 + (lane & 3) * 2;
        vr0[nb] = rec2(*(const uint32_t*)(vrow0 + d), *(const uint32_t*)(vrow0 + 64 + d));
        vr1[nb] = rec2(*(const uint32_t*)(vrow1 + d), *(const uint32_t*)(vrow1 + 64 + d));
        o[nb][0] *= inv0; o[nb][1] *= inv0; o[nb][2] *= inv1; o[nb][3] *= inv1;
        sov0 += o[nb][0] * vr0[nb].x + o[nb][1] * vr0[nb].y;
        svv0 += vr0[nb].x * vr0[nb].x + vr0[nb].y * vr0[nb].y;
        sov1 += o[nb][2] * vr1[nb].x + o[nb][3] * vr1[nb].y;
        svv1 += vr1[nb].x * vr1[nb].x + vr1[nb].y * vr1[nb].y;
    }
    sov0 += __shfl_xor_sync(0xffffffffu, sov0, 1);
    sov0 += __shfl_xor_sync(0xffffffffu, sov0, 2);
    svv0 += __shfl_xor_sync(0xffffffffu, svv0, 1);
    svv0 += __shfl_xor_sync(0xffffffffu, svv0, 2);
    sov1 += __shfl_xor_sync(0xffffffffu, sov1, 1);
    sov1 += __shfl_xor_sync(0xffffffffu, sov1, 2);
    svv1 += __shfl_xor_sync(0xffffffffu, svv1, 1);
    svv1 += __shfl_xor_sync(0xffffffffu, svv1, 2);

    float mx0 = fmaxf(sqrtf(svv0), 1e-12f);
    float mx1 = fmaxf(sqrtf(svv1), 1e-12f);
    float c0 = sov0 / (mx0 * mx0), c1 = sov1 / (mx1 * mx1);

    __nv_bfloat16* a0 = A3out + (size_t)(b * T_ + qrow_g0) * K3_;
    __nv_bfloat16* a1 = a0 + 8 * K3_;
    #pragma unroll
    for (int nb = 0; nb < 8; nb++) {
        int k = h * D_ + nb * 8 + (lane & 3) * 2;
        float y00 = o[nb][0] - c0 * vr0[nb].x, y01 = o[nb][1] - c0 * vr0[nb].y;
        float y10 = o[nb][2] - c1 * vr1[nb].x, y11 = o[nb][3] - c1 * vr1[nb].y;
        uint32_t lo0; uint32_t hi0 = split2(y00, y01, lo0);
        uint32_t lo1; uint32_t hi1 = split2(y10, y11, lo1);
        *(uint32_t*)(a0 + k)        = hi0;
        *(uint32_t*)(a0 + 1024 + k) = lo0;
        *(uint32_t*)(a0 + 2048 + k) = hi0;
        *(uint32_t*)(a1 + k)        = hi1;
        *(uint32_t*)(a1 + 1024 + k) = lo1;
        *(uint32_t*)(a1 + 2048 + k) = hi1;
    }
}

// ---------------------------------------------------------------------------
extern "C" void kernel_launch(void* const* d_in, const int* in_sizes, int n_in,
                              void* d_out, int out_size)
{
    const float* x  = (const float*)d_in[0];
    const float* Wa = (const float*)d_in[1];
    const float* ba = (const float*)d_in[2];
    const float* Wp = (const float*)d_in[3];
    const float* bp = (const float*)d_in[4];
    float* out = (float*)d_out;

    float* qkv;
    __nv_bfloat16 *A3, *B3, *Qp, *Kp, *Vp;
    cudaGetSymbolAddress((void**)&qkv, g_qkv);
    cudaGetSymbolAddress((void**)&A3,  g_A3);
    cudaGetSymbolAddress((void**)&B3,  g_B3);
    cudaGetSymbolAddress((void**)&Qp,  g_Q);
    cudaGetSymbolAddress((void**)&Kp,  g_K);
    cudaGetSymbolAddress((void**)&Vp,  g_V);

    const int M = B_ * T_;
    const int flash_smem = 2 * FBUF * 2;            // 69.6 KB
    const int gemm_smem  = NSTG * 2 * OPBYTES;      // 110.6 KB

    static int attr_set = 0;
    if (!attr_set) {
        cudaFuncSetAttribute(flash_hmma, cudaFuncAttributeMaxDynamicSharedMemorySize, flash_smem);
        cudaFuncSetAttribute(hmma_gemm,  cudaFuncAttributeMaxDynamicSharedMemorySize, gemm_smem);
        attr_set = 1;
    }

    prep_W<<<dim3(C3_ / 32, C_ / 32), 256>>>(Wa, B3, C3_);
    split_A<<<(M * C_) / (256 * 8), 256>>>(x, A3);
    hmma_gemm<<<dim3(C3_ / 128, M / 128), 256, gemm_smem>>>(A3, B3, ba, qkv, M, C3_, K3_);

    prep_qkv<<<(M * H_) / 8, 256>>>(qkv, Qp, Kp, Vp);

    flash_hmma<<<dim3(T_ / 128, H_, B_), 256, flash_smem>>>(Qp, Kp, Vp, A3);

    prep_W<<<dim3(C_ / 32, C_ / 32), 256>>>(Wp, B3, C_);
    hmma_gemm<<<dim3(C_ / 128, M / 128), 256, gemm_smem>>>(A3, B3, bp, out, M, C_, K3_);
}

// round 15
// speedup vs baseline: 1.7169x; 1.0118x over previous
#include <cuda_runtime.h>
#include <cuda_bf16.h>
#include <math.h>
#include <stdint.h>

#define B_  4
#define T_  2048
#define C_  1024
#define H_  16
#define D_  64
#define C3_ 3072
#define K3_ 3072

typedef unsigned long long u64;

__device__ float g_qkv[(size_t)B_ * T_ * C3_];
__device__ __nv_bfloat16 g_A3[(size_t)B_ * T_ * K3_];
__device__ __nv_bfloat16 g_B3[(size_t)C3_ * K3_];
__device__ __nv_bfloat16 g_Q[(size_t)B_ * H_ * T_ * 128];
__device__ __nv_bfloat16 g_K[(size_t)B_ * H_ * T_ * 128];
__device__ __nv_bfloat16 g_V[(size_t)B_ * H_ * T_ * 128];

// ---- helpers ----
__device__ __forceinline__ uint32_t smem_u32(const void* p) {
    uint32_t a;
    asm("{ .reg .u64 t; cvta.to.shared.u64 t, %1; cvt.u32.u64 %0, t; }" : "=r"(a) : "l"(p));
    return a;
}
__device__ __forceinline__ void cp16(uint32_t dst, const void* src) {
    asm volatile("cp.async.cg.shared.global [%0], [%1], 16;" :: "r"(dst), "l"(src));
}
__device__ __forceinline__ void ldsm_x4(uint32_t& r0, uint32_t& r1, uint32_t& r2, uint32_t& r3,
                                        uint32_t addr) {
    asm volatile("ldmatrix.sync.aligned.m8n8.x4.shared.b16 {%0,%1,%2,%3},[%4];"
                 : "=r"(r0), "=r"(r1), "=r"(r2), "=r"(r3) : "r"(addr));
}
__device__ __forceinline__ void ldsm_x4t(uint32_t& r0, uint32_t& r1, uint32_t& r2, uint32_t& r3,
                                         uint32_t addr) {
    asm volatile("ldmatrix.sync.aligned.m8n8.x4.trans.shared.b16 {%0,%1,%2,%3},[%4];"
                 : "=r"(r0), "=r"(r1), "=r"(r2), "=r"(r3) : "r"(addr));
}
__device__ __forceinline__ void mma16816(float* c, const uint32_t* a, uint32_t b0, uint32_t b1) {
    asm volatile(
        "mma.sync.aligned.m16n8k16.row.col.f32.bf16.bf16.f32 "
        "{%0,%1,%2,%3},{%4,%5,%6,%7},{%8,%9},{%0,%1,%2,%3};"
        : "+f"(c[0]), "+f"(c[1]), "+f"(c[2]), "+f"(c[3])
        : "r"(a[0]), "r"(a[1]), "r"(a[2]), "r"(a[3]), "r"(b0), "r"(b1));
}
__device__ __forceinline__ uint32_t pkbf(float lo, float hi) {
    uint32_t r; asm("cvt.rn.bf16x2.f32 %0,%1,%2;" : "=r"(r) : "f"(hi), "f"(lo)); return r;
}
__device__ __forceinline__ uint32_t split2(float a, float b, uint32_t& lo) {
    uint32_t hp = pkbf(a, b);
    float la = a - __uint_as_float(hp << 16);
    float lb = b - __uint_as_float(hp & 0xFFFF0000u);
    lo = pkbf(la, lb);
    return hp;
}
__device__ __forceinline__ uint2 split4(float4 f, uint2& lo) {
    uint32_t l0, l1;
    uint32_t h0 = split2(f.x, f.y, l0);
    uint32_t h1 = split2(f.z, f.w, l1);
    lo = make_uint2(l0, l1);
    return make_uint2(h0, h1);
}
__device__ __forceinline__ float2 rec2(uint32_t hw, uint32_t lw) {
    float2 r;
    r.x = __uint_as_float(hw << 16)          + __uint_as_float(lw << 16);
    r.y = __uint_as_float(hw & 0xFFFF0000u)  + __uint_as_float(lw & 0xFFFF0000u);
    return r;
}

// ---------------------------------------------------------------------------
// split_A: src fp32 [M,1024] -> dst bf16 [M,3072] = [hi|lo|hi]
// ---------------------------------------------------------------------------
__global__ __launch_bounds__(256) void split_A(
    const float* __restrict__ src, __nv_bfloat16* __restrict__ dst)
{
    size_t idx = ((size_t)blockIdx.x * 256 + threadIdx.x) * 8;
    int m = (int)(idx >> 10), k = (int)(idx & 1023);
    float4 f0 = *(const float4*)(src + idx);
    float4 f1 = *(const float4*)(src + idx + 4);
    uint2 l0, l1;
    uint2 h0 = split4(f0, l0);
    uint2 h1 = split4(f1, l1);
    __nv_bfloat16* r = dst + (size_t)m * K3_;
    *(uint4*)(r + k)        = make_uint4(h0.x, h0.y, h1.x, h1.y);
    *(uint4*)(r + 1024 + k) = make_uint4(l0.x, l0.y, l1.x, l1.y);
    *(uint4*)(r + 2048 + k) = make_uint4(h0.x, h0.y, h1.x, h1.y);
}

// ---------------------------------------------------------------------------
// prep_W: W fp32 [1024, N] -> Bo bf16 [N,3072] = [hi|hi|lo]
// ---------------------------------------------------------------------------
__global__ __launch_bounds__(256) void prep_W(
    const float* __restrict__ W, __nv_bfloat16* __restrict__ Bo, int N)
{
    __shared__ float t[32][33];
    int n0 = blockIdx.x * 32, k0 = blockIdx.y * 32;
    {
        int tx = threadIdx.x & 31, ty = threadIdx.x >> 5;
        #pragma unroll
        for (int i = 0; i < 4; i++)
            t[ty + i * 8][tx] = W[(size_t)(k0 + ty + i * 8) * N + n0 + tx];
    }
    __syncthreads();
    int kk = (threadIdx.x & 15) * 2, ny = threadIdx.x >> 4;
    #pragma unroll
    for (int i = 0; i < 2; i++) {
        int n = ny + i * 16;
        uint32_t lp;
        uint32_t hp = split2(t[kk][n], t[kk + 1][n], lp);
        size_t r = (size_t)(n0 + n) * K3_;
        *(uint32_t*)(Bo + r + k0 + kk)        = hp;
        *(uint32_t*)(Bo + r + 1024 + k0 + kk) = hp;
        *(uint32_t*)(Bo + r + 2048 + k0 + kk) = lp;
    }
}

// ---------------------------------------------------------------------------
// HMMA GEMM: 128x128 tile, BK=64, 3-stage cp.async, ONE sync per K-iter
// (prefetch issued after the consume barrier; in-order group completion
// makes the end-of-loop barrier redundant).
// ---------------------------------------------------------------------------
#define BK    64
#define ROWE  72
#define NSTG  3
#define OPBYTES (128 * ROWE * 2)

__global__ __launch_bounds__(256) void hmma_gemm(
    const __nv_bfloat16* __restrict__ A, const __nv_bfloat16* __restrict__ Bk,
    const float* __restrict__ bias, float* __restrict__ Cout,
    int M, int N, int K)
{
    extern __shared__ __align__(16) __nv_bfloat16 gsm[];

    const int tid  = threadIdx.x;
    const int lane = tid & 31;
    const int wid  = tid >> 5;
    const int wm   = wid >> 2;
    const int wn   = wid & 3;
    const int m0 = blockIdx.y * 128, n0 = blockIdx.x * 128;

    const uint32_t smb = smem_u32(gsm);

    auto load_tile = [&](int stg, int kt) {
        const __nv_bfloat16* Ag = A + (size_t)m0 * K + kt * BK;
        const __nv_bfloat16* Bg = Bk + (size_t)n0 * K + kt * BK;
        uint32_t sA = smb + stg * (2 * OPBYTES);
        uint32_t sB = sA + OPBYTES;
        #pragma unroll
        for (int it = 0; it < 4; it++) {
            int c = tid + it * 256;
            int row = c >> 3, seg = c & 7;
            uint32_t doff = (uint32_t)(row * ROWE + seg * 8) * 2;
            cp16(sA + doff, Ag + (size_t)row * K + seg * 8);
            cp16(sB + doff, Bg + (size_t)row * K + seg * 8);
        }
        asm volatile("cp.async.commit_group;" ::: "memory");
    };

    float acc[4][4][4];
    #pragma unroll
    for (int i = 0; i < 4; i++)
        #pragma unroll
        for (int j = 0; j < 4; j++)
            #pragma unroll
            for (int e = 0; e < 4; e++) acc[i][j][e] = 0.f;

    const int nkt = K / BK;
    load_tile(0, 0);
    load_tile(1, 1);

    const int a_row = wm * 64 + (lane & 15);
    const int a_ko  = (lane >> 4) * 8;
    const int b_row = wn * 32 + (lane & 7) + ((lane >> 4) & 1) * 8;
    const int b_ko  = ((lane >> 3) & 1) * 8;

    int stg = 0;
    for (int kt = 0; kt < nkt; kt++) {
        // all groups except the newest are complete -> stage stg is ready
        asm volatile("cp.async.wait_group 1;" ::: "memory");
        __syncthreads();

        // issue prefetch AFTER the barrier: every warp has finished reading
        // the stage this load overwrites (consumed at iteration kt-1).
        if (kt + 2 < nkt) {
            int s2 = stg + 2; if (s2 >= NSTG) s2 -= NSTG;
            load_tile(s2, kt + 2);
        } else {
            asm volatile("cp.async.commit_group;" ::: "memory");  // keep FIFO count
        }

        const uint32_t aT = smb + stg * (2 * OPBYTES);
        const uint32_t bT = aT + OPBYTES;

        #pragma unroll
        for (int ks = 0; ks < 4; ks++) {
            uint32_t af[4][4];
            #pragma unroll
            for (int mi = 0; mi < 4; mi++)
                ldsm_x4(af[mi][0], af[mi][1], af[mi][2], af[mi][3],
                        aT + (uint32_t)((a_row + mi * 16) * ROWE + ks * 16 + a_ko) * 2);
            uint32_t bf[4][2];
            #pragma unroll
            for (int nb = 0; nb < 2; nb++) {
                uint32_t r0, r1, r2, r3;
                ldsm_x4(r0, r1, r2, r3,
                        bT + (uint32_t)((b_row + nb * 16) * ROWE + ks * 16 + b_ko) * 2);
                bf[nb * 2][0] = r0; bf[nb * 2][1] = r1;
                bf[nb * 2 + 1][0] = r2; bf[nb * 2 + 1][1] = r3;
            }
            #pragma unroll
            for (int mi = 0; mi < 4; mi++)
                #pragma unroll
                for (int ni = 0; ni < 4; ni++)
                    mma16816(acc[mi][ni], af[mi], bf[ni][0], bf[ni][1]);
        }
        if (++stg >= NSTG) stg = 0;
    }

    #pragma unroll
    for (int mi = 0; mi < 4; mi++) {
        int row_g = m0 + wm * 64 + mi * 16 + (lane >> 2);
        #pragma unroll
        for (int ni = 0; ni < 4; ni++) {
            int col_g = n0 + wn * 32 + ni * 8 + (lane & 3) * 2;
            float b0 = bias[col_g], b1 = bias[col_g + 1];
            float2 o0 = make_float2(acc[mi][ni][0] + b0, acc[mi][ni][1] + b1);
            float2 o1 = make_float2(acc[mi][ni][2] + b0, acc[mi][ni][3] + b1);
            *(float2*)(Cout + (size_t)row_g * N + col_g) = o0;
            *(float2*)(Cout + (size_t)(row_g + 8) * N + col_g) = o1;
        }
    }
}

// ---------------------------------------------------------------------------
// prep_qkv: warp per (b,t,h) row.
// ---------------------------------------------------------------------------
__global__ __launch_bounds__(256) void prep_qkv(
    const float* __restrict__ qkv,
    __nv_bfloat16* __restrict__ Qo, __nv_bfloat16* __restrict__ Ko,
    __nv_bfloat16* __restrict__ Vo)
{
    const int lane = threadIdx.x & 31;
    const int wrp  = threadIdx.x >> 5;
    const size_t row = (size_t)blockIdx.x * 8 + wrp;
    const size_t bt  = row >> 4;
    const int    h   = (int)(row & 15);
    const int    b   = (int)(bt >> 11);
    const int    t   = (int)(bt & 2047);
    const size_t orow = ((size_t)(b * H_ + h) * T_ + t) * 128;

    {
        const float* pq = qkv + bt * C3_ + h * D_;
        float2 q = *(const float2*)(pq + 2 * lane);
        uint32_t qlo; uint32_t qhi = split2(q.x * 0.125f, q.y * 0.125f, qlo);
        __nv_bfloat16* qr = Qo + orow;
        *(uint32_t*)(qr + 2 * lane)      = qhi;
        *(uint32_t*)(qr + 64 + 2 * lane) = qlo;
    }

    const float* pk = qkv + bt * C3_ + C_ + h * D_;
    float2 z = *(const float2*)(pk + 2 * lane);
    float v0 = z.x, v1 = z.y;

    #pragma unroll
    for (int k = 2; k <= 64; k <<= 1) {
        #pragma unroll
        for (int j = k >> 1; j > 0; j >>= 1) {
            if (j < 32) {
                float p0 = __shfl_xor_sync(0xffffffffu, v0, j);
                float p1 = __shfl_xor_sync(0xffffffffu, v1, j);
                bool lower = (lane & j) == 0;
                bool up0 = (lane & k) != 0;
                bool up1 = ((lane + 32) & k) != 0;
                v0 = (lower == up0) ? fminf(v0, p0) : fmaxf(v0, p0);
                v1 = (lower == up1) ? fminf(v1, p1) : fmaxf(v1, p1);
            } else {
                float a = fmaxf(v0, v1), bmin = fminf(v0, v1);
                v0 = a; v1 = bmin;
            }
        }
    }

    float c0 = v0;
    #pragma unroll
    for (int o = 1; o < 32; o <<= 1) {
        float tt = __shfl_up_sync(0xffffffffu, c0, o);
        if (lane >= o) c0 += tt;
    }
    float c1 = v1;
    #pragma unroll
    for (int o = 1; o < 32; o <<= 1) {
        float tt = __shfl_up_sync(0xffffffffu, c1, o);
        if (lane >= o) c1 += tt;
    }
    c1 += __shfl_sync(0xffffffffu, c0, 31);

    bool s0 = 1.f + (float)(lane + 1)  * v0 > c0;
    bool s1 = 1.f + (float)(lane + 33) * v1 > c1;
    int rho = __popc(__ballot_sync(0xffffffffu, s0)) +
              __popc(__ballot_sync(0xffffffffu, s1));
    int ridx = rho - 1;
    float csA = __shfl_sync(0xffffffffu, c0, ridx & 31);
    float csB = __shfl_sync(0xffffffffu, c1, ridx & 31);
    float cs  = (ridx < 32) ? csA : csB;
    float tau = (cs - 1.f) / (float)rho;

    float k0 = fmaxf(z.x - tau, 0.f), k1 = fmaxf(z.y - tau, 0.f);
    uint32_t klo; uint32_t khi = split2(k0, k1, klo);
    __nv_bfloat16* kr = Ko + orow;
    *(uint32_t*)(kr + 2 * lane)      = khi;
    *(uint32_t*)(kr + 64 + 2 * lane) = klo;

    float2 vv = *(const float2*)(pk + C_ + 2 * lane);
    uint32_t vlo; uint32_t vhi = split2(vv.x, vv.y, vlo);
    __nv_bfloat16* vr = Vo + orow;
    *(uint32_t*)(vr + 2 * lane)      = vhi;
    *(uint32_t*)(vr + 64 + 2 * lane) = vlo;
}

// ---------------------------------------------------------------------------
// Flash attention: pure cp.async consumer, ONE sync per KV-iter (prefetch
// issued after the consume barrier), LPT ordering, deduped ldsm, JIT P-split,
// 2 CTAs/SM, XSA from bf16 V, split-A3 epilogue.
// ---------------------------------------------------------------------------
#define FROW 136
#define FBUF (128 * FROW)

__global__ __launch_bounds__(256, 2) void flash_hmma(
    const __nv_bfloat16* __restrict__ Qs,
    const __nv_bfloat16* __restrict__ Ks, const __nv_bfloat16* __restrict__ Vs,
    __nv_bfloat16* __restrict__ A3out)
{
    extern __shared__ __align__(16) __nv_bfloat16 smx[];

    const int tid  = threadIdx.x;
    const int lane = tid & 31;
    const int w    = tid >> 5;
    const int qt = (int)gridDim.x - 1 - (int)blockIdx.x;
    const int h = blockIdx.y, b = blockIdx.z;

    const size_t plane = (size_t)(b * H_ + h) * T_;
    const __nv_bfloat16* Kb = Ks + plane * 128;
    const __nv_bfloat16* Vb = Vs + plane * 128;
    const uint32_t smb0 = smem_u32(smx);

    auto load_tile = [&](int buf, int kt) {
        const __nv_bfloat16* kg = Kb + (size_t)kt * 64 * 128;
        const __nv_bfloat16* vg = Vb + (size_t)kt * 64 * 128;
        uint32_t sb = smb0 + buf * (FBUF * 2);
        #pragma unroll
        for (int it = 0; it < 4; it++) {
            int c = tid + it * 256;
            int j = c >> 4, seg = c & 15;
            cp16(sb + (uint32_t)(j * FROW) * 2 + seg * 16,        kg + j * 128 + seg * 8);
            cp16(sb + (uint32_t)((64 + j) * FROW) * 2 + seg * 16, vg + j * 128 + seg * 8);
        }
        asm volatile("cp.async.commit_group;" ::: "memory");
    };

    // tile0 K/V + Q tile (128 rows x 256B) via cp.async
    load_tile(0, 0);
    {
        const __nv_bfloat16* qg = Qs + (plane + (size_t)qt * 128) * 128;
        uint32_t qb = smb0 + FBUF * 2;
        #pragma unroll
        for (int it = 0; it < 8; it++) {
            int c = tid + it * 256;
            int row = c >> 4, seg = c & 15;
            cp16(qb + (uint32_t)(row * FROW) * 2 + seg * 16, qg + row * 128 + seg * 8);
        }
        asm volatile("cp.async.commit_group;" ::: "memory");
    }
    asm volatile("cp.async.wait_group 0;" ::: "memory");
    __syncthreads();

    uint32_t qf[8][4];
    #pragma unroll
    for (int kb = 0; kb < 8; kb++) {
        uint32_t addr = smb0 + FBUF * 2 +
                        (uint32_t)((w * 16 + (lane & 15)) * FROW + kb * 16 + (lane >> 4) * 8) * 2;
        ldsm_x4(qf[kb][0], qf[kb][1], qf[kb][2], qf[kb][3], addr);
    }

    float o[8][4];
    #pragma unroll
    for (int nb = 0; nb < 8; nb++)
        #pragma unroll
        for (int e = 0; e < 4; e++) o[nb][e] = 0.f;
    float m0 = -1e30f, m1 = -1e30f, l0 = 0.f, l1 = 0.f;

    const int qrow_g0 = qt * 128 + w * 16 + (lane >> 2);
    const int nkt = (qt + 1) * 2;

    for (int kt = 0; kt < nkt; kt++) {
        // all tile groups complete (distance-1 double buffer)
        asm volatile("cp.async.wait_group 0;" ::: "memory");
        __syncthreads();

        // prefetch next tile AFTER the barrier: its target buffer was
        // consumed by every warp at iteration kt-1.
        if (kt + 1 < nkt) load_tile((kt + 1) & 1, kt + 1);

        const uint32_t smb = smb0 + (kt & 1) * (FBUF * 2);

        // ---- S = Qh·Kh + Ql·Kh + Qh·Kl ----
        float s[8][4];
        #pragma unroll
        for (int nb = 0; nb < 8; nb++)
            #pragma unroll
            for (int e = 0; e < 4; e++) s[nb][e] = 0.f;

        #pragma unroll
        for (int j = 0; j < 4; j++) {
            #pragma unroll
            for (int nbp = 0; nbp < 4; nbp++) {
                uint32_t r0, r1, r2, r3;
                uint32_t addr = smb +
                    (uint32_t)((nbp * 16 + (lane & 7) + ((lane >> 4) & 1) * 8) * FROW
                               + j * 16 + ((lane >> 3) & 1) * 8) * 2;
                ldsm_x4(r0, r1, r2, r3, addr);
                mma16816(s[nbp * 2],     qf[j],     r0, r1);
                mma16816(s[nbp * 2 + 1], qf[j],     r2, r3);
                mma16816(s[nbp * 2],     qf[j + 4], r0, r1);
                mma16816(s[nbp * 2 + 1], qf[j + 4], r2, r3);
            }
        }
        #pragma unroll
        for (int j = 0; j < 4; j++) {
            #pragma unroll
            for (int nbp = 0; nbp < 4; nbp++) {
                uint32_t r0, r1, r2, r3;
                uint32_t addr = smb +
                    (uint32_t)((nbp * 16 + (lane & 7) + ((lane >> 4) & 1) * 8) * FROW
                               + 64 + j * 16 + ((lane >> 3) & 1) * 8) * 2;
                ldsm_x4(r0, r1, r2, r3, addr);
                mma16816(s[nbp * 2],     qf[j], r0, r1);
                mma16816(s[nbp * 2 + 1], qf[j], r2, r3);
            }
        }

        // ---- causal mask ----
        if (kt * 64 + 63 > qt * 128 + w * 16) {
            #pragma unroll
            for (int nb = 0; nb < 8; nb++) {
                int col = kt * 64 + nb * 8 + (lane & 3) * 2;
                if (col     > qrow_g0)     s[nb][0] = -1e30f;
                if (col + 1 > qrow_g0)     s[nb][1] = -1e30f;
                if (col     > qrow_g0 + 8) s[nb][2] = -1e30f;
                if (col + 1 > qrow_g0 + 8) s[nb][3] = -1e30f;
            }
        }

        // ---- online softmax ----
        float tm0 = -1e30f, tm1 = -1e30f;
        #pragma unroll
        for (int nb = 0; nb < 8; nb++) {
            tm0 = fmaxf(tm0, fmaxf(s[nb][0], s[nb][1]));
            tm1 = fmaxf(tm1, fmaxf(s[nb][2], s[nb][3]));
        }
        tm0 = fmaxf(tm0, __shfl_xor_sync(0xffffffffu, tm0, 1));
        tm0 = fmaxf(tm0, __shfl_xor_sync(0xffffffffu, tm0, 2));
        tm1 = fmaxf(tm1, __shfl_xor_sync(0xffffffffu, tm1, 1));
        tm1 = fmaxf(tm1, __shfl_xor_sync(0xffffffffu, tm1, 2));

        float m0n = fmaxf(m0, tm0), m1n = fmaxf(m1, tm1);
        float corr0 = __expf(m0 - m0n), corr1 = __expf(m1 - m1n);
        m0 = m0n; m1 = m1n;
        l0 *= corr0; l1 *= corr1;

        #pragma unroll
        for (int nb = 0; nb < 8; nb++) {
            s[nb][0] = __expf(s[nb][0] - m0);
            s[nb][1] = __expf(s[nb][1] - m0);
            s[nb][2] = __expf(s[nb][2] - m1);
            s[nb][3] = __expf(s[nb][3] - m1);
            l0 += s[nb][0] + s[nb][1];
            l1 += s[nb][2] + s[nb][3];
            o[nb][0] *= corr0; o[nb][1] *= corr0;
            o[nb][2] *= corr1; o[nb][3] *= corr1;
        }

        // ---- O += Ph·Vh + Pl·Vh + Ph·Vl ----
        #pragma unroll
        for (int j = 0; j < 4; j++) {
            uint32_t ph[4], pl[4];
            #pragma unroll
            for (int q = 0; q < 4; q++) {
                int nb = j * 2 + (q >> 1);
                uint32_t plq;
                ph[q] = split2(s[nb][(q & 1) * 2], s[nb][(q & 1) * 2 + 1], plq);
                pl[q] = plq;
            }
            int krow = 64 + j * 16;
            #pragma unroll
            for (int nbp = 0; nbp < 4; nbp++) {
                uint32_t r0, r1, r2, r3;
                uint32_t addr = smb +
                    (uint32_t)((krow + (lane & 15)) * FROW + nbp * 16 + (lane >> 4) * 8) * 2;
                ldsm_x4t(r0, r1, r2, r3, addr);
                mma16816(o[nbp * 2],     ph, r0, r1);
                mma16816(o[nbp * 2 + 1], ph, r2, r3);
                mma16816(o[nbp * 2],     pl, r0, r1);
                mma16816(o[nbp * 2 + 1], pl, r2, r3);
            }
            #pragma unroll
            for (int nbp = 0; nbp < 4; nbp++) {
                uint32_t r0, r1, r2, r3;
                uint32_t addr = smb +
                    (uint32_t)((krow + (lane & 15)) * FROW + 64 + nbp * 16 + (lane >> 4) * 8) * 2;
                ldsm_x4t(r0, r1, r2, r3, addr);
                mma16816(o[nbp * 2],     ph, r0, r1);
                mma16816(o[nbp * 2 + 1], ph, r2, r3);
            }
        }
    }

    // ---- finalize: normalize + XSA (V reconstructed from bf16 hi+lo) ----
    l0 += __shfl_xor_sync(0xffffffffu, l0, 1);
    l0 += __shfl_xor_sync(0xffffffffu, l0, 2);
    l1 += __shfl_xor_sync(0xffffffffu, l1, 1);
    l1 += __shfl_xor_sync(0xffffffffu, l1, 2);
    float inv0 = 1.f / l0, inv1 = 1.f / l1;

    const __nv_bfloat16* vrow0 = Vb + (size_t)qrow_g0 * 128;
    const __nv_bfloat16* vrow1 = vrow0 + 8 * 128;

    float2 vr0[8], vr1[8];
    float sov0 = 0.f, svv0 = 0.f, sov1 = 0.f, svv1 = 0.f;
    #pragma unroll
    for (int nb = 0; nb < 8; nb++) {
        int d = nb * 8 + (lane & 3) * 2;
        vr0[nb] = rec2(*(const uint32_t*)(vrow0 + d), *(const uint32_t*)(vrow0 + 64 + d));
        vr1[nb] = rec2(*(const uint32_t*)(vrow1 + d), *(const uint32_t*)(vrow1 + 64 + d));
        o[nb][0] *= inv0; o[nb][1] *= inv0; o[nb][2] *= inv1; o[nb][3] *= inv1;
        sov0 += o[nb][0] * vr0[nb].x + o[nb][1] * vr0[nb].y;
        svv0 += vr0[nb].x * vr0[nb].x + vr0[nb].y * vr0[nb].y;
        sov1 += o[nb][2] * vr1[nb].x + o[nb][3] * vr1[nb].y;
        svv1 += vr1[nb].x * vr1[nb].x + vr1[nb].y * vr1[nb].y;
    }
    sov0 += __shfl_xor_sync(0xffffffffu, sov0, 1);
    sov0 += __shfl_xor_sync(0xffffffffu, sov0, 2);
    svv0 += __shfl_xor_sync(0xffffffffu, svv0, 1);
    svv0 += __shfl_xor_sync(0xffffffffu, svv0, 2);
    sov1 += __shfl_xor_sync(0xffffffffu, sov1, 1);
    sov1 += __shfl_xor_sync(0xffffffffu, sov1, 2);
    svv1 += __shfl_xor_sync(0xffffffffu, svv1, 1);
    svv1 += __shfl_xor_sync(0xffffffffu, svv1, 2);

    float mx0 = fmaxf(sqrtf(svv0), 1e-12f);
    float mx1 = fmaxf(sqrtf(svv1), 1e-12f);
    float c0 = sov0 / (mx0 * mx0), c1 = sov1 / (mx1 * mx1);

    __nv_bfloat16* a0 = A3out + (size_t)(b * T_ + qrow_g0) * K3_;
    __nv_bfloat16* a1 = a0 + 8 * K3_;
    #pragma unroll
    for (int nb = 0; nb < 8; nb++) {
        int k = h * D_ + nb * 8 + (lane & 3) * 2;
        float y00 = o[nb][0] - c0 * vr0[nb].x, y01 = o[nb][1] - c0 * vr0[nb].y;
        float y10 = o[nb][2] - c1 * vr1[nb].x, y11 = o[nb][3] - c1 * vr1[nb].y;
        uint32_t lo0; uint32_t hi0 = split2(y00, y01, lo0);
        uint32_t lo1; uint32_t hi1 = split2(y10, y11, lo1);
        *(uint32_t*)(a0 + k)        = hi0;
        *(uint32_t*)(a0 + 1024 + k) = lo0;
        *(uint32_t*)(a0 + 2048 + k) = hi0;
        *(uint32_t*)(a1 + k)        = hi1;
        *(uint32_t*)(a1 + 1024 + k) = lo1;
        *(uint32_t*)(a1 + 2048 + k) = hi1;
    }
}

// ---------------------------------------------------------------------------
extern "C" void kernel_launch(void* const* d_in, const int* in_sizes, int n_in,
                              void* d_out, int out_size)
{
    const float* x  = (const float*)d_in[0];
    const float* Wa = (const float*)d_in[1];
    const float* ba = (const float*)d_in[2];
    const float* Wp = (const float*)d_in[3];
    const float* bp = (const float*)d_in[4];
    float* out = (float*)d_out;

    float* qkv;
    __nv_bfloat16 *A3, *B3, *Qp, *Kp, *Vp;
    cudaGetSymbolAddress((void**)&qkv, g_qkv);
    cudaGetSymbolAddress((void**)&A3,  g_A3);
    cudaGetSymbolAddress((void**)&B3,  g_B3);
    cudaGetSymbolAddress((void**)&Qp,  g_Q);
    cudaGetSymbolAddress((void**)&Kp,  g_K);
    cudaGetSymbolAddress((void**)&Vp,  g_V);

    const int M = B_ * T_;
    const int flash_smem = 2 * FBUF * 2;            // 69.6 KB
    const int gemm_smem  = NSTG * 2 * OPBYTES;      // 110.6 KB

    static int attr_set = 0;
    if (!attr_set) {
        cudaFuncSetAttribute(flash_hmma, cudaFuncAttributeMaxDynamicSharedMemorySize, flash_smem);
        cudaFuncSetAttribute(hmma_gemm,  cudaFuncAttributeMaxDynamicSharedMemorySize, gemm_smem);
        attr_set = 1;
    }

    prep_W<<<dim3(C3_ / 32, C_ / 32), 256>>>(Wa, B3, C3_);
    split_A<<<(M * C_) / (256 * 8), 256>>>(x, A3);
    hmma_gemm<<<dim3(C3_ / 128, M / 128), 256, gemm_smem>>>(A3, B3, ba, qkv, M, C3_, K3_);

    prep_qkv<<<(M * H_) / 8, 256>>>(qkv, Qp, Kp, Vp);

    flash_hmma<<<dim3(T_ / 128, H_, B_), 256, flash_smem>>>(Qp, Kp, Vp, A3);

    prep_W<<<dim3(C_ / 32, C_ / 32), 256>>>(Wp, B3, C_);
    hmma_gemm<<<dim3(C_ / 128, M / 128), 256, gemm_smem>>>(A3, B3, bp, out, M, C_, K3_);
}

// round 16
// speedup vs baseline: 1.7178x; 1.0005x over previous
#include <cuda_runtime.h>
#include <cuda_bf16.h>
#include <math.h>
#include <stdint.h>

#define B_  4
#define T_  2048
#define C_  1024
#define H_  16
#define D_  64
#define C3_ 3072
#define K3_ 3072

typedef unsigned long long u64;

__device__ float g_qkv[(size_t)B_ * T_ * C3_];
__device__ __nv_bfloat16 g_A3[(size_t)B_ * T_ * K3_];
__device__ __nv_bfloat16 g_B3[(size_t)C3_ * K3_];
__device__ __nv_bfloat16 g_Q[(size_t)B_ * H_ * T_ * 128];
__device__ __nv_bfloat16 g_K[(size_t)B_ * H_ * T_ * 128];
__device__ __nv_bfloat16 g_V[(size_t)B_ * H_ * T_ * 128];

// ---- helpers ----
__device__ __forceinline__ uint32_t smem_u32(const void* p) {
    uint32_t a;
    asm("{ .reg .u64 t; cvta.to.shared.u64 t, %1; cvt.u32.u64 %0, t; }" : "=r"(a) : "l"(p));
    return a;
}
__device__ __forceinline__ void cp16(uint32_t dst, const void* src) {
    asm volatile("cp.async.cg.shared.global [%0], [%1], 16;" :: "r"(dst), "l"(src));
}
__device__ __forceinline__ void ldsm_x4(uint32_t& r0, uint32_t& r1, uint32_t& r2, uint32_t& r3,
                                        uint32_t addr) {
    asm volatile("ldmatrix.sync.aligned.m8n8.x4.shared.b16 {%0,%1,%2,%3},[%4];"
                 : "=r"(r0), "=r"(r1), "=r"(r2), "=r"(r3) : "r"(addr));
}
__device__ __forceinline__ void ldsm_x4t(uint32_t& r0, uint32_t& r1, uint32_t& r2, uint32_t& r3,
                                         uint32_t addr) {
    asm volatile("ldmatrix.sync.aligned.m8n8.x4.trans.shared.b16 {%0,%1,%2,%3},[%4];"
                 : "=r"(r0), "=r"(r1), "=r"(r2), "=r"(r3) : "r"(addr));
}
__device__ __forceinline__ void mma16816(float* c, const uint32_t* a, uint32_t b0, uint32_t b1) {
    asm volatile(
        "mma.sync.aligned.m16n8k16.row.col.f32.bf16.bf16.f32 "
        "{%0,%1,%2,%3},{%4,%5,%6,%7},{%8,%9},{%0,%1,%2,%3};"
        : "+f"(c[0]), "+f"(c[1]), "+f"(c[2]), "+f"(c[3])
        : "r"(a[0]), "r"(a[1]), "r"(a[2]), "r"(a[3]), "r"(b0), "r"(b1));
}
__device__ __forceinline__ uint32_t pkbf(float lo, float hi) {
    uint32_t r; asm("cvt.rn.bf16x2.f32 %0,%1,%2;" : "=r"(r) : "f"(hi), "f"(lo)); return r;
}
__device__ __forceinline__ uint32_t split2(float a, float b, uint32_t& lo) {
    uint32_t hp = pkbf(a, b);
    float la = a - __uint_as_float(hp << 16);
    float lb = b - __uint_as_float(hp & 0xFFFF0000u);
    lo = pkbf(la, lb);
    return hp;
}
__device__ __forceinline__ uint2 split4(float4 f, uint2& lo) {
    uint32_t l0, l1;
    uint32_t h0 = split2(f.x, f.y, l0);
    uint32_t h1 = split2(f.z, f.w, l1);
    lo = make_uint2(l0, l1);
    return make_uint2(h0, h1);
}
__device__ __forceinline__ float2 rec2(uint32_t hw, uint32_t lw) {
    float2 r;
    r.x = __uint_as_float(hw << 16)          + __uint_as_float(lw << 16);
    r.y = __uint_as_float(hw & 0xFFFF0000u)  + __uint_as_float(lw & 0xFFFF0000u);
    return r;
}

// ---- prep bodies (shared-by-pointer so fused kernels can reuse) ----
__device__ __forceinline__ void split_A_body(
    const float* __restrict__ src, __nv_bfloat16* __restrict__ dst, int bidx)
{
    size_t idx = ((size_t)bidx * 256 + threadIdx.x) * 8;
    int m = (int)(idx >> 10), k = (int)(idx & 1023);
    float4 f0 = *(const float4*)(src + idx);
    float4 f1 = *(const float4*)(src + idx + 4);
    uint2 l0, l1;
    uint2 h0 = split4(f0, l0);
    uint2 h1 = split4(f1, l1);
    __nv_bfloat16* r = dst + (size_t)m * K3_;
    *(uint4*)(r + k)        = make_uint4(h0.x, h0.y, h1.x, h1.y);
    *(uint4*)(r + 1024 + k) = make_uint4(l0.x, l0.y, l1.x, l1.y);
    *(uint4*)(r + 2048 + k) = make_uint4(h0.x, h0.y, h1.x, h1.y);
}

__device__ __forceinline__ void prep_W_body(
    const float* __restrict__ W, __nv_bfloat16* __restrict__ Bo, int N,
    int bidx, float (*t)[33])
{
    const int nblk = N / 32;
    int n0 = (bidx % nblk) * 32, k0 = (bidx / nblk) * 32;
    {
        int tx = threadIdx.x & 31, ty = threadIdx.x >> 5;
        #pragma unroll
        for (int i = 0; i < 4; i++)
            t[ty + i * 8][tx] = W[(size_t)(k0 + ty + i * 8) * N + n0 + tx];
    }
    __syncthreads();
    int kk = (threadIdx.x & 15) * 2, ny = threadIdx.x >> 4;
    #pragma unroll
    for (int i = 0; i < 2; i++) {
        int n = ny + i * 16;
        uint32_t lp;
        uint32_t hp = split2(t[kk][n], t[kk + 1][n], lp);
        size_t r = (size_t)(n0 + n) * K3_;
        *(uint32_t*)(Bo + r + k0 + kk)        = hp;
        *(uint32_t*)(Bo + r + 1024 + k0 + kk) = hp;
        *(uint32_t*)(Bo + r + 2048 + k0 + kk) = lp;
    }
}

__device__ __forceinline__ void prep_qkv_body(
    const float* __restrict__ qkv,
    __nv_bfloat16* __restrict__ Qo, __nv_bfloat16* __restrict__ Ko,
    __nv_bfloat16* __restrict__ Vo, int bidx)
{
    const int lane = threadIdx.x & 31;
    const int wrp  = threadIdx.x >> 5;
    const size_t row = (size_t)bidx * 8 + wrp;
    const size_t bt  = row >> 4;
    const int    h   = (int)(row & 15);
    const int    b   = (int)(bt >> 11);
    const int    t   = (int)(bt & 2047);
    const size_t orow = ((size_t)(b * H_ + h) * T_ + t) * 128;

    {
        const float* pq = qkv + bt * C3_ + h * D_;
        float2 q = *(const float2*)(pq + 2 * lane);
        uint32_t qlo; uint32_t qhi = split2(q.x * 0.125f, q.y * 0.125f, qlo);
        __nv_bfloat16* qr = Qo + orow;
        *(uint32_t*)(qr + 2 * lane)      = qhi;
        *(uint32_t*)(qr + 64 + 2 * lane) = qlo;
    }

    const float* pk = qkv + bt * C3_ + C_ + h * D_;
    float2 z = *(const float2*)(pk + 2 * lane);
    float v0 = z.x, v1 = z.y;

    #pragma unroll
    for (int k = 2; k <= 64; k <<= 1) {
        #pragma unroll
        for (int j = k >> 1; j > 0; j >>= 1) {
            if (j < 32) {
                float p0 = __shfl_xor_sync(0xffffffffu, v0, j);
                float p1 = __shfl_xor_sync(0xffffffffu, v1, j);
                bool lower = (lane & j) == 0;
                bool up0 = (lane & k) != 0;
                bool up1 = ((lane + 32) & k) != 0;
                v0 = (lower == up0) ? fminf(v0, p0) : fmaxf(v0, p0);
                v1 = (lower == up1) ? fminf(v1, p1) : fmaxf(v1, p1);
            } else {
                float a = fmaxf(v0, v1), bmin = fminf(v0, v1);
                v0 = a; v1 = bmin;
            }
        }
    }

    float c0 = v0;
    #pragma unroll
    for (int o = 1; o < 32; o <<= 1) {
        float tt = __shfl_up_sync(0xffffffffu, c0, o);
        if (lane >= o) c0 += tt;
    }
    float c1 = v1;
    #pragma unroll
    for (int o = 1; o < 32; o <<= 1) {
        float tt = __shfl_up_sync(0xffffffffu, c1, o);
        if (lane >= o) c1 += tt;
    }
    c1 += __shfl_sync(0xffffffffu, c0, 31);

    bool s0 = 1.f + (float)(lane + 1)  * v0 > c0;
    bool s1 = 1.f + (float)(lane + 33) * v1 > c1;
    int rho = __popc(__ballot_sync(0xffffffffu, s0)) +
              __popc(__ballot_sync(0xffffffffu, s1));
    int ridx = rho - 1;
    float csA = __shfl_sync(0xffffffffu, c0, ridx & 31);
    float csB = __shfl_sync(0xffffffffu, c1, ridx & 31);
    float cs  = (ridx < 32) ? csA : csB;
    float tau = (cs - 1.f) / (float)rho;

    float k0 = fmaxf(z.x - tau, 0.f), k1 = fmaxf(z.y - tau, 0.f);
    uint32_t klo; uint32_t khi = split2(k0, k1, klo);
    __nv_bfloat16* kr = Ko + orow;
    *(uint32_t*)(kr + 2 * lane)      = khi;
    *(uint32_t*)(kr + 64 + 2 * lane) = klo;

    float2 vv = *(const float2*)(pk + C_ + 2 * lane);
    uint32_t vlo; uint32_t vhi = split2(vv.x, vv.y, vlo);
    __nv_bfloat16* vr = Vo + orow;
    *(uint32_t*)(vr + 2 * lane)      = vhi;
    *(uint32_t*)(vr + 64 + 2 * lane) = vlo;
}

// ---------------------------------------------------------------------------
// fused_prep1: blocks [0, NA) do split_A(x); blocks [NA, NA+3072) do prep_W(Wa).
// Branch uniform per block -> internal __syncthreads is safe.
// ---------------------------------------------------------------------------
#define NA_BLOCKS ((B_ * T_ * C_) / (256 * 8))     // 4096
#define WA_BLOCKS ((C3_ / 32) * (C_ / 32))          // 3072

__global__ __launch_bounds__(256) void fused_prep1(
    const float* __restrict__ x, const float* __restrict__ Wa,
    __nv_bfloat16* __restrict__ A3, __nv_bfloat16* __restrict__ B3)
{
    __shared__ float t[32][33];
    if (blockIdx.x < NA_BLOCKS) split_A_body(x, A3, blockIdx.x);
    else                        prep_W_body(Wa, B3, C3_, blockIdx.x - NA_BLOCKS, t);
}

// ---------------------------------------------------------------------------
// fused_prep2: blocks [0, NQ) do prep_qkv; blocks [NQ, NQ+1024) do prep_W(Wp).
// g_B3 is dead after GEMM-1, safe to overwrite here.
// ---------------------------------------------------------------------------
#define NQ_BLOCKS ((B_ * T_ * H_) / 8)              // 16384
#define WP_BLOCKS ((C_ / 32) * (C_ / 32))           // 1024

__global__ __launch_bounds__(256) void fused_prep2(
    const float* __restrict__ qkv,
    __nv_bfloat16* __restrict__ Qo, __nv_bfloat16* __restrict__ Ko,
    __nv_bfloat16* __restrict__ Vo,
    const float* __restrict__ Wp, __nv_bfloat16* __restrict__ B3)
{
    __shared__ float t[32][33];
    if (blockIdx.x < NQ_BLOCKS) prep_qkv_body(qkv, Qo, Ko, Vo, blockIdx.x);
    else                        prep_W_body(Wp, B3, C_, blockIdx.x - NQ_BLOCKS, t);
}

// ---------------------------------------------------------------------------
// HMMA GEMM: 128x128 tile, BK=64, 3-stage cp.async, one sync per K-iter.
// ---------------------------------------------------------------------------
#define BK    64
#define ROWE  72
#define NSTG  3
#define OPBYTES (128 * ROWE * 2)

__global__ __launch_bounds__(256) void hmma_gemm(
    const __nv_bfloat16* __restrict__ A, const __nv_bfloat16* __restrict__ Bk,
    const float* __restrict__ bias, float* __restrict__ Cout,
    int M, int N, int K)
{
    extern __shared__ __align__(16) __nv_bfloat16 gsm[];

    const int tid  = threadIdx.x;
    const int lane = tid & 31;
    const int wid  = tid >> 5;
    const int wm   = wid >> 2;
    const int wn   = wid & 3;
    const int m0 = blockIdx.y * 128, n0 = blockIdx.x * 128;

    const uint32_t smb = smem_u32(gsm);

    auto load_tile = [&](int stg, int kt) {
        const __nv_bfloat16* Ag = A + (size_t)m0 * K + kt * BK;
        const __nv_bfloat16* Bg = Bk + (size_t)n0 * K + kt * BK;
        uint32_t sA = smb + stg * (2 * OPBYTES);
        uint32_t sB = sA + OPBYTES;
        #pragma unroll
        for (int it = 0; it < 4; it++) {
            int c = tid + it * 256;
            int row = c >> 3, seg = c & 7;
            uint32_t doff = (uint32_t)(row * ROWE + seg * 8) * 2;
            cp16(sA + doff, Ag + (size_t)row * K + seg * 8);
            cp16(sB + doff, Bg + (size_t)row * K + seg * 8);
        }
        asm volatile("cp.async.commit_group;" ::: "memory");
    };

    float acc[4][4][4];
    #pragma unroll
    for (int i = 0; i < 4; i++)
        #pragma unroll
        for (int j = 0; j < 4; j++)
            #pragma unroll
            for (int e = 0; e < 4; e++) acc[i][j][e] = 0.f;

    const int nkt = K / BK;
    load_tile(0, 0);
    load_tile(1, 1);

    const int a_row = wm * 64 + (lane & 15);
    const int a_ko  = (lane >> 4) * 8;
    const int b_row = wn * 32 + (lane & 7) + ((lane >> 4) & 1) * 8;
    const int b_ko  = ((lane >> 3) & 1) * 8;

    int stg = 0;
    for (int kt = 0; kt < nkt; kt++) {
        asm volatile("cp.async.wait_group 1;" ::: "memory");
        __syncthreads();

        if (kt + 2 < nkt) {
            int s2 = stg + 2; if (s2 >= NSTG) s2 -= NSTG;
            load_tile(s2, kt + 2);
        } else {
            asm volatile("cp.async.commit_group;" ::: "memory");
        }

        const uint32_t aT = smb + stg * (2 * OPBYTES);
        const uint32_t bT = aT + OPBYTES;

        #pragma unroll
        for (int ks = 0; ks < 4; ks++) {
            uint32_t af[4][4];
            #pragma unroll
            for (int mi = 0; mi < 4; mi++)
                ldsm_x4(af[mi][0], af[mi][1], af[mi][2], af[mi][3],
                        aT + (uint32_t)((a_row + mi * 16) * ROWE + ks * 16 + a_ko) * 2);
            uint32_t bf[4][2];
            #pragma unroll
            for (int nb = 0; nb < 2; nb++) {
                uint32_t r0, r1, r2, r3;
                ldsm_x4(r0, r1, r2, r3,
                        bT + (uint32_t)((b_row + nb * 16) * ROWE + ks * 16 + b_ko) * 2);
                bf[nb * 2][0] = r0; bf[nb * 2][1] = r1;
                bf[nb * 2 + 1][0] = r2; bf[nb * 2 + 1][1] = r3;
            }
            #pragma unroll
            for (int mi = 0; mi < 4; mi++)
                #pragma unroll
                for (int ni = 0; ni < 4; ni++)
                    mma16816(acc[mi][ni], af[mi], bf[ni][0], bf[ni][1]);
        }
        if (++stg >= NSTG) stg = 0;
    }

    #pragma unroll
    for (int mi = 0; mi < 4; mi++) {
        int row_g = m0 + wm * 64 + mi * 16 + (lane >> 2);
        #pragma unroll
        for (int ni = 0; ni < 4; ni++) {
            int col_g = n0 + wn * 32 + ni * 8 + (lane & 3) * 2;
            float b0 = bias[col_g], b1 = bias[col_g + 1];
            float2 o0 = make_float2(acc[mi][ni][0] + b0, acc[mi][ni][1] + b1);
            float2 o1 = make_float2(acc[mi][ni][2] + b0, acc[mi][ni][3] + b1);
            *(float2*)(Cout + (size_t)row_g * N + col_g) = o0;
            *(float2*)(Cout + (size_t)(row_g + 8) * N + col_g) = o1;
        }
    }
}

// ---------------------------------------------------------------------------
// Flash attention (unchanged from r15).
// ---------------------------------------------------------------------------
#define FROW 136
#define FBUF (128 * FROW)

__global__ __launch_bounds__(256, 2) void flash_hmma(
    const __nv_bfloat16* __restrict__ Qs,
    const __nv_bfloat16* __restrict__ Ks, const __nv_bfloat16* __restrict__ Vs,
    __nv_bfloat16* __restrict__ A3out)
{
    extern __shared__ __align__(16) __nv_bfloat16 smx[];

    const int tid  = threadIdx.x;
    const int lane = tid & 31;
    const int w    = tid >> 5;
    const int qt = (int)gridDim.x - 1 - (int)blockIdx.x;
    const int h = blockIdx.y, b = blockIdx.z;

    const size_t plane = (size_t)(b * H_ + h) * T_;
    const __nv_bfloat16* Kb = Ks + plane * 128;
    const __nv_bfloat16* Vb = Vs + plane * 128;
    const uint32_t smb0 = smem_u32(smx);

    auto load_tile = [&](int buf, int kt) {
        const __nv_bfloat16* kg = Kb + (size_t)kt * 64 * 128;
        const __nv_bfloat16* vg = Vb + (size_t)kt * 64 * 128;
        uint32_t sb = smb0 + buf * (FBUF * 2);
        #pragma unroll
        for (int it = 0; it < 4; it++) {
            int c = tid + it * 256;
            int j = c >> 4, seg = c & 15;
            cp16(sb + (uint32_t)(j * FROW) * 2 + seg * 16,        kg + j * 128 + seg * 8);
            cp16(sb + (uint32_t)((64 + j) * FROW) * 2 + seg * 16, vg + j * 128 + seg * 8);
        }
        asm volatile("cp.async.commit_group;" ::: "memory");
    };

    load_tile(0, 0);
    {
        const __nv_bfloat16* qg = Qs + (plane + (size_t)qt * 128) * 128;
        uint32_t qb = smb0 + FBUF * 2;
        #pragma unroll
        for (int it = 0; it < 8; it++) {
            int c = tid + it * 256;
            int row = c >> 4, seg = c & 15;
            cp16(qb + (uint32_t)(row * FROW) * 2 + seg * 16, qg + row * 128 + seg * 8);
        }
        asm volatile("cp.async.commit_group;" ::: "memory");
    }
    asm volatile("cp.async.wait_group 0;" ::: "memory");
    __syncthreads();

    uint32_t qf[8][4];
    #pragma unroll
    for (int kb = 0; kb < 8; kb++) {
        uint32_t addr = smb0 + FBUF * 2 +
                        (uint32_t)((w * 16 + (lane & 15)) * FROW + kb * 16 + (lane >> 4) * 8) * 2;
        ldsm_x4(qf[kb][0], qf[kb][1], qf[kb][2], qf[kb][3], addr);
    }

    float o[8][4];
    #pragma unroll
    for (int nb = 0; nb < 8; nb++)
        #pragma unroll
        for (int e = 0; e < 4; e++) o[nb][e] = 0.f;
    float m0 = -1e30f, m1 = -1e30f, l0 = 0.f, l1 = 0.f;

    const int qrow_g0 = qt * 128 + w * 16 + (lane >> 2);
    const int nkt = (qt + 1) * 2;

    for (int kt = 0; kt < nkt; kt++) {
        asm volatile("cp.async.wait_group 0;" ::: "memory");
        __syncthreads();

        if (kt + 1 < nkt) load_tile((kt + 1) & 1, kt + 1);

        const uint32_t smb = smb0 + (kt & 1) * (FBUF * 2);

        float s[8][4];
        #pragma unroll
        for (int nb = 0; nb < 8; nb++)
            #pragma unroll
            for (int e = 0; e < 4; e++) s[nb][e] = 0.f;

        #pragma unroll
        for (int j = 0; j < 4; j++) {
            #pragma unroll
            for (int nbp = 0; nbp < 4; nbp++) {
                uint32_t r0, r1, r2, r3;
                uint32_t addr = smb +
                    (uint32_t)((nbp * 16 + (lane & 7) + ((lane >> 4) & 1) * 8) * FROW
                               + j * 16 + ((lane >> 3) & 1) * 8) * 2;
                ldsm_x4(r0, r1, r2, r3, addr);
                mma16816(s[nbp * 2],     qf[j],     r0, r1);
                mma16816(s[nbp * 2 + 1], qf[j],     r2, r3);
                mma16816(s[nbp * 2],     qf[j + 4], r0, r1);
                mma16816(s[nbp * 2 + 1], qf[j + 4], r2, r3);
            }
        }
        #pragma unroll
        for (int j = 0; j < 4; j++) {
            #pragma unroll
            for (int nbp = 0; nbp < 4; nbp++) {
                uint32_t r0, r1, r2, r3;
                uint32_t addr = smb +
                    (uint32_t)((nbp * 16 + (lane & 7) + ((lane >> 4) & 1) * 8) * FROW
                               + 64 + j * 16 + ((lane >> 3) & 1) * 8) * 2;
                ldsm_x4(r0, r1, r2, r3, addr);
                mma16816(s[nbp * 2],     qf[j], r0, r1);
                mma16816(s[nbp * 2 + 1], qf[j], r2, r3);
            }
        }

        if (kt * 64 + 63 > qt * 128 + w * 16) {
            #pragma unroll
            for (int nb = 0; nb < 8; nb++) {
                int col = kt * 64 + nb * 8 + (lane & 3) * 2;
                if (col     > qrow_g0)     s[nb][0] = -1e30f;
                if (col + 1 > qrow_g0)     s[nb][1] = -1e30f;
                if (col     > qrow_g0 + 8) s[nb][2] = -1e30f;
                if (col + 1 > qrow_g0 + 8) s[nb][3] = -1e30f;
            }
        }

        float tm0 = -1e30f, tm1 = -1e30f;
        #pragma unroll
        for (int nb = 0; nb < 8; nb++) {
            tm0 = fmaxf(tm0, fmaxf(s[nb][0], s[nb][1]));
            tm1 = fmaxf(tm1, fmaxf(s[nb][2], s[nb][3]));
        }
        tm0 = fmaxf(tm0, __shfl_xor_sync(0xffffffffu, tm0, 1));
        tm0 = fmaxf(tm0, __shfl_xor_sync(0xffffffffu, tm0, 2));
        tm1 = fmaxf(tm1, __shfl_xor_sync(0xffffffffu, tm1, 1));
        tm1 = fmaxf(tm1, __shfl_xor_sync(0xffffffffu, tm1, 2));

        float m0n = fmaxf(m0, tm0), m1n = fmaxf(m1, tm1);
        float corr0 = __expf(m0 - m0n), corr1 = __expf(m1 - m1n);
        m0 = m0n; m1 = m1n;
        l0 *= corr0; l1 *= corr1;

        #pragma unroll
        for (int nb = 0; nb < 8; nb++) {
            s[nb][0] = __expf(s[nb][0] - m0);
            s[nb][1] = __expf(s[nb][1] - m0);
            s[nb][2] = __expf(s[nb][2] - m1);
            s[nb][3] = __expf(s[nb][3] - m1);
            l0 += s[nb][0] + s[nb][1];
            l1 += s[nb][2] + s[nb][3];
            o[nb][0] *= corr0; o[nb][1] *= corr0;
            o[nb][2] *= corr1; o[nb][3] *= corr1;
        }

        #pragma unroll
        for (int j = 0; j < 4; j++) {
            uint32_t ph[4], pl[4];
            #pragma unroll
            for (int q = 0; q < 4; q++) {
                int nb = j * 2 + (q >> 1);
                uint32_t plq;
                ph[q] = split2(s[nb][(q & 1) * 2], s[nb][(q & 1) * 2 + 1], plq);
                pl[q] = plq;
            }
            int krow = 64 + j * 16;
            #pragma unroll
            for (int nbp = 0; nbp < 4; nbp++) {
                uint32_t r0, r1, r2, r3;
                uint32_t addr = smb +
                    (uint32_t)((krow + (lane & 15)) * FROW + nbp * 16 + (lane >> 4) * 8) * 2;
                ldsm_x4t(r0, r1, r2, r3, addr);
                mma16816(o[nbp * 2],     ph, r0, r1);
                mma16816(o[nbp * 2 + 1], ph, r2, r3);
                mma16816(o[nbp * 2],     pl, r0, r1);
                mma16816(o[nbp * 2 + 1], pl, r2, r3);
            }
            #pragma unroll
            for (int nbp = 0; nbp < 4; nbp++) {
                uint32_t r0, r1, r2, r3;
                uint32_t addr = smb +
                    (uint32_t)((krow + (lane & 15)) * FROW + 64 + nbp * 16 + (lane >> 4) * 8) * 2;
                ldsm_x4t(r0, r1, r2, r3, addr);
                mma16816(o[nbp * 2],     ph, r0, r1);
                mma16816(o[nbp * 2 + 1], ph, r2, r3);
            }
        }
    }

    l0 += __shfl_xor_sync(0xffffffffu, l0, 1);
    l0 += __shfl_xor_sync(0xffffffffu, l0, 2);
    l1 += __shfl_xor_sync(0xffffffffu, l1, 1);
    l1 += __shfl_xor_sync(0xffffffffu, l1, 2);
    float inv0 = 1.f / l0, inv1 = 1.f / l1;

    const __nv_bfloat16* vrow0 = Vb + (size_t)qrow_g0 * 128;
    const __nv_bfloat16* vrow1 = vrow0 + 8 * 128;

    float2 vr0[8], vr1[8];
    float sov0 = 0.f, svv0 = 0.f, sov1 = 0.f, svv1 = 0.f;
    #pragma unroll
    for (int nb = 0; nb < 8; nb++) {
        int d = nb * 8 + (lane & 3) * 2;
        vr0[nb] = rec2(*(const uint32_t*)(vrow0 + d), *(const uint32_t*)(vrow0 + 64 + d));
        vr1[nb] = rec2(*(const uint32_t*)(vrow1 + d), *(const uint32_t*)(vrow1 + 64 + d));
        o[nb][0] *= inv0; o[nb][1] *= inv0; o[nb][2] *= inv1; o[nb][3] *= inv1;
        sov0 += o[nb][0] * vr0[nb].x + o[nb][1] * vr0[nb].y;
        svv0 += vr0[nb].x * vr0[nb].x + vr0[nb].y * vr0[nb].y;
        sov1 += o[nb][2] * vr1[nb].x + o[nb][3] * vr1[nb].y;
        svv1 += vr1[nb].x * vr1[nb].x + vr1[nb].y * vr1[nb].y;
    }
    sov0 += __shfl_xor_sync(0xffffffffu, sov0, 1);
    sov0 += __shfl_xor_sync(0xffffffffu, sov0, 2);
    svv0 += __shfl_xor_sync(0xffffffffu, svv0, 1);
    svv0 += __shfl_xor_sync(0xffffffffu, svv0, 2);
    sov1 += __shfl_xor_sync(0xffffffffu, sov1, 1);
    sov1 += __shfl_xor_sync(0xffffffffu, sov1, 2);
    svv1 += __shfl_xor_sync(0xffffffffu, svv1, 1);
    svv1 += __shfl_xor_sync(0xffffffffu, svv1, 2);

    float mx0 = fmaxf(sqrtf(svv0), 1e-12f);
    float mx1 = fmaxf(sqrtf(svv1), 1e-12f);
    float c0 = sov0 / (mx0 * mx0), c1 = sov1 / (mx1 * mx1);

    __nv_bfloat16* a0 = A3out + (size_t)(b * T_ + qrow_g0) * K3_;
    __nv_bfloat16* a1 = a0 + 8 * K3_;
    #pragma unroll
    for (int nb = 0; nb < 8; nb++) {
        int k = h * D_ + nb * 8 + (lane & 3) * 2;
        float y00 = o[nb][0] - c0 * vr0[nb].x, y01 = o[nb][1] - c0 * vr0[nb].y;
        float y10 = o[nb][2] - c1 * vr1[nb].x, y11 = o[nb][3] - c1 * vr1[nb].y;
        uint32_t lo0; uint32_t hi0 = split2(y00, y01, lo0);
        uint32_t lo1; uint32_t hi1 = split2(y10, y11, lo1);
        *(uint32_t*)(a0 + k)        = hi0;
        *(uint32_t*)(a0 + 1024 + k) = lo0;
        *(uint32_t*)(a0 + 2048 + k) = hi0;
        *(uint32_t*)(a1 + k)        = hi1;
        *(uint32_t*)(a1 + 1024 + k) = lo1;
        *(uint32_t*)(a1 + 2048 + k) = hi1;
    }
}

// ---------------------------------------------------------------------------
extern "C" void kernel_launch(void* const* d_in, const int* in_sizes, int n_in,
                              void* d_out, int out_size)
{
    const float* x  = (const float*)d_in[0];
    const float* Wa = (const float*)d_in[1];
    const float* ba = (const float*)d_in[2];
    const float* Wp = (const float*)d_in[3];
    const float* bp = (const float*)d_in[4];
    float* out = (float*)d_out;

    float* qkv;
    __nv_bfloat16 *A3, *B3, *Qp, *Kp, *Vp;
    cudaGetSymbolAddress((void**)&qkv, g_qkv);
    cudaGetSymbolAddress((void**)&A3,  g_A3);
    cudaGetSymbolAddress((void**)&B3,  g_B3);
    cudaGetSymbolAddress((void**)&Qp,  g_Q);
    cudaGetSymbolAddress((void**)&Kp,  g_K);
    cudaGetSymbolAddress((void**)&Vp,  g_V);

    const int M = B_ * T_;
    const int flash_smem = 2 * FBUF * 2;            // 69.6 KB
    const int gemm_smem  = NSTG * 2 * OPBYTES;      // 110.6 KB

    static int attr_set = 0;
    if (!attr_set) {
        cudaFuncSetAttribute(flash_hmma, cudaFuncAttributeMaxDynamicSharedMemorySize, flash_smem);
        cudaFuncSetAttribute(hmma_gemm,  cudaFuncAttributeMaxDynamicSharedMemorySize, gemm_smem);
        attr_set = 1;
    }

    // prep for GEMM-1: split_A(x) + prep_W(Wa) co-scheduled in one launch
    fused_prep1<<<NA_BLOCKS + WA_BLOCKS, 256>>>(x, Wa, A3, B3);
    hmma_gemm<<<dim3(C3_ / 128, M / 128), 256, gemm_smem>>>(A3, B3, ba, qkv, M, C3_, K3_);

    // prep for flash + prep_W(Wp) (g_B3 free after GEMM-1) in one launch
    fused_prep2<<<NQ_BLOCKS + WP_BLOCKS, 256>>>(qkv, Qp, Kp, Vp, Wp, B3);

    flash_hmma<<<dim3(T_ / 128, H_, B_), 256, flash_smem>>>(Qp, Kp, Vp, A3);

    hmma_gemm<<<dim3(C_ / 128, M / 128), 256, gemm_smem>>>(A3, B3, bp, out, M, C_, K3_);
}